// round 2
// baseline (speedup 1.0000x reference)
#include <cuda_runtime.h>
#include <math.h>

// ---------------- problem constants ----------------
#define QLEN   1024
#define BSZ    4
#define DMODEL 1024
#define NHEAD  16
#define DHEAD  64
#define DINNER 4096
#define MEMLEN 1024
#define KLEN   2048          // QLEN + MEMLEN
#define LN_EPS 1e-5f

// ---------------- scratch (device globals; no allocation allowed) ----------------
__device__ float g_wheads [(size_t)8192 * 3072];        // cat @ qkv_w   [row=j*B+b][3*1024]
__device__ float g_rheadk [(size_t)2048 * 1024];        // r @ r_net_w   [jj][n*64+d]
__device__ float g_scores [(size_t)64 * 1024 * 2048];   // [(b*16+n)][i][j]
__device__ float g_attnvec[(size_t)4096 * 1024];        // [i*B+b][n*64+d]
__device__ float g_pre    [(size_t)4096 * 1024];        // pre-layernorm buffer (reused)
__device__ float g_out1   [(size_t)4096 * 1024];        // LN1 output (also FFN residual)
__device__ float g_ffh    [(size_t)4096 * 4096];        // relu(out1@ff_w1+b1)

// compile-time buffer selector (avoids cudaGetSymbolAddress during capture)
__device__ __forceinline__ float* gbuf(int id) {
    switch (id) {
        case 0: return g_wheads;
        case 1: return g_rheadk;
        case 2: return g_attnvec;
        case 3: return g_pre;
        case 4: return g_out1;
        case 5: return g_ffh;
    }
    return nullptr;
}

// ---------------- generic tiled fp32 GEMM ----------------
// C[Mr,Nc] = A[Mr,Kd] @ B[Kd,Nc]  (+ bias / relu / residual)
// 128x128 block, BK=16, 256 threads, 8x8 micro-tile.
// A rows gathered: row < Asplit -> A1, else A2 (for mems||w concat).
// EPI: 0 = plain, 1 = bias+relu, 2 = bias+resid, 3 = resid
template<int EPI, int AID, int CID, int RID>
__global__ __launch_bounds__(256, 2)
void gemm_k(const float* __restrict__ A1p, const float* __restrict__ A2p, int Asplit,
            const float* __restrict__ B, int Nc, int Kd,
            const float* __restrict__ bias, const float* __restrict__ residp)
{
    const float* A1 = (AID >= 0) ? gbuf(AID) : A1p;
    const float* A2 = A2p;
    float*       C  = gbuf(CID);
    const float* RS = (RID >= 0) ? gbuf(RID) : residp;

    __shared__ float As[16][132];   // transposed A tile (padded)
    __shared__ float Bs[16][128];

    const int tid  = threadIdx.x;
    const int row0 = blockIdx.y * 128;
    const int col0 = blockIdx.x * 128;
    const int tr   = (tid >> 4) << 3;   // 0..120
    const int tc   = (tid & 15) << 3;

    float acc[8][8];
    #pragma unroll
    for (int i = 0; i < 8; i++)
        #pragma unroll
        for (int j = 0; j < 8; j++) acc[i][j] = 0.f;

    for (int k0 = 0; k0 < Kd; k0 += 16) {
        #pragma unroll
        for (int l = 0; l < 2; l++) {
            int v  = l * 256 + tid;
            // A: 128 rows x 4 float4
            int r  = v >> 2, c4 = v & 3;
            int gr = row0 + r;
            const float* src = (gr < Asplit) ? (A1 + (size_t)gr * Kd)
                                             : (A2 + (size_t)(gr - Asplit) * Kd);
            float4 fa = *(const float4*)(src + k0 + c4 * 4);
            As[c4 * 4 + 0][r] = fa.x;
            As[c4 * 4 + 1][r] = fa.y;
            As[c4 * 4 + 2][r] = fa.z;
            As[c4 * 4 + 3][r] = fa.w;
            // B: 16 rows x 32 float4
            int rb = v >> 5, cb = v & 31;
            float4 fb = *(const float4*)(B + (size_t)(k0 + rb) * Nc + col0 + cb * 4);
            *(float4*)&Bs[rb][cb * 4] = fb;
        }
        __syncthreads();
        #pragma unroll
        for (int kk = 0; kk < 16; kk++) {
            float4 a0 = *(const float4*)&As[kk][tr];
            float4 a1 = *(const float4*)&As[kk][tr + 4];
            float4 b0 = *(const float4*)&Bs[kk][tc];
            float4 b1 = *(const float4*)&Bs[kk][tc + 4];
            float a[8] = {a0.x, a0.y, a0.z, a0.w, a1.x, a1.y, a1.z, a1.w};
            float b[8] = {b0.x, b0.y, b0.z, b0.w, b1.x, b1.y, b1.z, b1.w};
            #pragma unroll
            for (int i = 0; i < 8; i++)
                #pragma unroll
                for (int j = 0; j < 8; j++) acc[i][j] += a[i] * b[j];
        }
        __syncthreads();
    }

    #pragma unroll
    for (int i = 0; i < 8; i++) {
        int gr = row0 + tr + i;
        float* crow = C + (size_t)gr * Nc + col0 + tc;
        const float* rrow = (EPI == 2 || EPI == 3)
                          ? (RS + (size_t)gr * Nc + col0 + tc) : nullptr;
        #pragma unroll
        for (int j = 0; j < 8; j++) {
            float v = acc[i][j];
            if (EPI == 1 || EPI == 2) v += bias[col0 + tc + j];
            if (EPI == 1) v = fmaxf(v, 0.f);
            if (EPI == 2 || EPI == 3) v += rrow[j];
            crow[j] = v;
        }
    }
}

// ---------------- fused AC + BD score kernel ----------------
// score[i,j] = (q_i.k_j + rwb.k_j + q_i.r_d + rrb.r_d) * scale,  d = j - i + Q - 1
// masked (j > i+M) -> -1e30
__global__ __launch_bounds__(256)
void score_k(const float* __restrict__ rwbias, const float* __restrict__ rrbias)
{
    const int jt = blockIdx.x, it = blockIdx.y;
    const int n  = blockIdx.z & 15, b = blockIdx.z >> 4;
    const int i0 = it * 64, j0 = jt * 64;
    const int tid = threadIdx.x;
    float* out = g_scores + ((size_t)blockIdx.z * QLEN + i0) * KLEN + j0;

    if (j0 > i0 + 63 + MEMLEN) {            // fully masked tile: just fill
        #pragma unroll
        for (int e = 0; e < 16; e++) {
            int idx = e * 256 + tid;
            out[(size_t)(idx >> 6) * KLEN + (idx & 63)] = -1e30f;
        }
        return;
    }

    __shared__ __align__(16) float Qs[64][36];
    __shared__ __align__(16) float Ks[64][36];
    __shared__ __align__(16) float Rs[128][36];
    __shared__ float c1[64], c2[128], wb[64], rb[64];

    if (tid < 64)       wb[tid]      = rwbias[n * 64 + tid];
    else if (tid < 128) rb[tid - 64] = rrbias[n * 64 + tid - 64];

    const int ti4  = (tid >> 4) << 2;
    const int tj4  = (tid & 15) << 2;
    const int base = 63 + tj4 - ti4;                 // d - r_lo for (ii=jj=0)
    const int r_lo = (QLEN - 1) + j0 - i0 - 63;      // >= 0 always

    float ac[4][4] = {}, bd[4][4] = {};
    float c1r = 0.f, c2r = 0.f;

    for (int h = 0; h < 2; h++) {                    // K-dim halves of 32
        __syncthreads();
        #pragma unroll
        for (int l = 0; l < 2; l++) {
            int v = l * 256 + tid;
            int rr = v >> 3, c4 = v & 7;
            int qrow = (MEMLEN + i0 + rr) * BSZ + b;
            float4 fq = *(const float4*)(g_wheads + (size_t)qrow * 3072 + n * 64 + h * 32 + c4 * 4);
            *(float4*)&Qs[rr][c4 * 4] = fq;
            int krow = (j0 + rr) * BSZ + b;
            float4 fk = *(const float4*)(g_wheads + (size_t)krow * 3072 + 1024 + n * 64 + h * 32 + c4 * 4);
            *(float4*)&Ks[rr][c4 * 4] = fk;
        }
        #pragma unroll
        for (int l = 0; l < 4; l++) {
            int v = l * 256 + tid;
            int rr = v >> 3, c4 = v & 7;
            int grow = r_lo + rr; if (grow > KLEN - 1) grow = KLEN - 1;  // OOB rows only feed masked elems
            float4 fr = *(const float4*)(g_rheadk + (size_t)grow * 1024 + n * 64 + h * 32 + c4 * 4);
            *(float4*)&Rs[rr][c4 * 4] = fr;
        }
        __syncthreads();

        if (tid < 64) {
            #pragma unroll
            for (int kk = 0; kk < 32; kk++) c1r += wb[h * 32 + kk] * Ks[tid][kk];
        } else if (tid < 192) {
            #pragma unroll
            for (int kk = 0; kk < 32; kk++) c2r += rb[h * 32 + kk] * Rs[tid - 64][kk];
        }

        #pragma unroll
        for (int k4 = 0; k4 < 8; k4++) {
            float4 aa[4], kv[4], rv[7];
            #pragma unroll
            for (int ii = 0; ii < 4; ii++) aa[ii] = *(const float4*)&Qs[ti4 + ii][k4 * 4];
            #pragma unroll
            for (int jj = 0; jj < 4; jj++) kv[jj] = *(const float4*)&Ks[tj4 + jj][k4 * 4];
            #pragma unroll
            for (int s = 0; s < 7; s++)   rv[s] = *(const float4*)&Rs[base - 3 + s][k4 * 4];
            #pragma unroll
            for (int ii = 0; ii < 4; ii++)
                #pragma unroll
                for (int jj = 0; jj < 4; jj++) {
                    float4 a4 = aa[ii], k4v = kv[jj], r4 = rv[3 + jj - ii];
                    ac[ii][jj] += a4.x * k4v.x + a4.y * k4v.y + a4.z * k4v.z + a4.w * k4v.w;
                    bd[ii][jj] += a4.x * r4.x  + a4.y * r4.y  + a4.z * r4.z  + a4.w * r4.w;
                }
        }
    }

    if (tid < 64)       c1[tid]      = c1r;
    else if (tid < 192) c2[tid - 64] = c2r;
    __syncthreads();

    const float scale = 0.125f;   // 1/sqrt(64)
    #pragma unroll
    for (int ii = 0; ii < 4; ii++) {
        int i = i0 + ti4 + ii;
        #pragma unroll
        for (int jj = 0; jj < 4; jj++) {
            int j = j0 + tj4 + jj;
            float s = (ac[ii][jj] + bd[ii][jj] + c1[tj4 + jj] + c2[base + jj - ii]) * scale;
            if (j > i + MEMLEN) s = -1e30f;
            out[(size_t)(ti4 + ii) * KLEN + tj4 + jj] = s;
        }
    }
}

// ---------------- row softmax over KLEN=2048 ----------------
__global__ __launch_bounds__(256)
void softmax_k()
{
    float* row = g_scores + (size_t)blockIdx.x * KLEN;
    const int tid = threadIdx.x;
    float v[8];
    #pragma unroll
    for (int e = 0; e < 8; e++) v[e] = row[e * 256 + tid];

    float m = v[0];
    #pragma unroll
    for (int e = 1; e < 8; e++) m = fmaxf(m, v[e]);
    #pragma unroll
    for (int off = 16; off; off >>= 1) m = fmaxf(m, __shfl_xor_sync(0xffffffffu, m, off));
    __shared__ float sm[8], ss[8];
    if ((tid & 31) == 0) sm[tid >> 5] = m;
    __syncthreads();
    float M = sm[0];
    #pragma unroll
    for (int w = 1; w < 8; w++) M = fmaxf(M, sm[w]);

    float s = 0.f;
    #pragma unroll
    for (int e = 0; e < 8; e++) { v[e] = __expf(v[e] - M); s += v[e]; }
    #pragma unroll
    for (int off = 16; off; off >>= 1) s += __shfl_xor_sync(0xffffffffu, s, off);
    if ((tid & 31) == 0) ss[tid >> 5] = s;
    __syncthreads();
    float S = 0.f;
    #pragma unroll
    for (int w = 0; w < 8; w++) S += ss[w];
    float inv = 1.f / S;
    #pragma unroll
    for (int e = 0; e < 8; e++) row[e * 256 + tid] = v[e] * inv;
}

// ---------------- P @ V per (b, n) ----------------
__global__ __launch_bounds__(256, 2)
void pv_k()
{
    const int it = blockIdx.x;
    const int n  = blockIdx.y & 15, b = blockIdx.y >> 4;
    const int i0 = it * 64;
    const int tid = threadIdx.x;
    __shared__ __align__(16) float Ps [64][68];
    __shared__ __align__(16) float VsT[64][68];   // transposed: [d][j]
    const int ti4 = (tid >> 4) << 2;
    const int tj4 = (tid & 15) << 2;
    float acc[4][4] = {};

    const int jtiles = ((i0 + 63 + MEMLEN) >> 6) + 1;   // skip fully-masked (P==0) tiles
    const float* sc = g_scores + ((size_t)blockIdx.y * QLEN + i0) * KLEN;

    for (int jt = 0; jt < jtiles; jt++) {
        int j0 = jt * 64;
        __syncthreads();
        #pragma unroll
        for (int l = 0; l < 4; l++) {
            int v = l * 256 + tid;
            int rr = v >> 4, c4 = v & 15;
            float4 fp = *(const float4*)(sc + (size_t)rr * KLEN + j0 + c4 * 4);
            *(float4*)&Ps[rr][c4 * 4] = fp;
            float4 fv = *(const float4*)(g_wheads + (size_t)((j0 + rr) * BSZ + b) * 3072
                                         + 2048 + n * 64 + c4 * 4);
            VsT[c4 * 4 + 0][rr] = fv.x;
            VsT[c4 * 4 + 1][rr] = fv.y;
            VsT[c4 * 4 + 2][rr] = fv.z;
            VsT[c4 * 4 + 3][rr] = fv.w;
        }
        __syncthreads();
        #pragma unroll
        for (int k4 = 0; k4 < 16; k4++) {
            float4 aa[4], bb[4];
            #pragma unroll
            for (int ii = 0; ii < 4; ii++) aa[ii] = *(const float4*)&Ps[ti4 + ii][k4 * 4];
            #pragma unroll
            for (int jj = 0; jj < 4; jj++) bb[jj] = *(const float4*)&VsT[tj4 + jj][k4 * 4];
            #pragma unroll
            for (int ii = 0; ii < 4; ii++)
                #pragma unroll
                for (int jj = 0; jj < 4; jj++)
                    acc[ii][jj] += aa[ii].x * bb[jj].x + aa[ii].y * bb[jj].y
                                 + aa[ii].z * bb[jj].z + aa[ii].w * bb[jj].w;
        }
    }
    #pragma unroll
    for (int ii = 0; ii < 4; ii++)
        #pragma unroll
        for (int jj = 0; jj < 4; jj++)
            g_attnvec[(size_t)((i0 + ti4 + ii) * BSZ + b) * 1024 + n * 64 + tj4 + jj] = acc[ii][jj];
}

// ---------------- layernorm over D=1024 ----------------
// src is always g_pre; dst = yext if non-null, else g_out1
__global__ __launch_bounds__(256)
void ln_k(float* __restrict__ yext, const float* __restrict__ gam, const float* __restrict__ bet)
{
    const float* row = g_pre + (size_t)blockIdx.x * DMODEL;
    float* orow = (yext ? yext : g_out1) + (size_t)blockIdx.x * DMODEL;
    const int tid = threadIdx.x;
    float v[4];
    float s = 0.f, sq = 0.f;
    #pragma unroll
    for (int e = 0; e < 4; e++) {
        v[e] = row[e * 256 + tid];
        s  += v[e];
        sq += v[e] * v[e];
    }
    #pragma unroll
    for (int off = 16; off; off >>= 1) {
        s  += __shfl_xor_sync(0xffffffffu, s,  off);
        sq += __shfl_xor_sync(0xffffffffu, sq, off);
    }
    __shared__ float sm[8], sm2[8];
    if ((tid & 31) == 0) { sm[tid >> 5] = s; sm2[tid >> 5] = sq; }
    __syncthreads();
    float S = 0.f, SQ = 0.f;
    #pragma unroll
    for (int w = 0; w < 8; w++) { S += sm[w]; SQ += sm2[w]; }
    const float mu  = S * (1.f / DMODEL);
    const float var = SQ * (1.f / DMODEL) - mu * mu;
    const float inv = rsqrtf(var + LN_EPS);
    #pragma unroll
    for (int e = 0; e < 4; e++) {
        int c = e * 256 + tid;
        orow[c] = (v[e] - mu) * inv * gam[c] + bet[c];
    }
}

// ---------------- launch ----------------
extern "C" void kernel_launch(void* const* d_in, const int* in_sizes, int n_in,
                              void* d_out, int out_size)
{
    const float* w        = (const float*)d_in[0];   // [1024,4,1024]
    const float* r        = (const float*)d_in[1];   // [2048,1,1024]
    const float* mems     = (const float*)d_in[2];   // [1024,4,1024]
    const float* qkv_w    = (const float*)d_in[3];   // [1024,3072]
    const float* r_net_w  = (const float*)d_in[4];   // [1024,1024]
    const float* o_w      = (const float*)d_in[5];   // [1024,1024]
    const float* r_w_bias = (const float*)d_in[6];   // [16,64]
    const float* r_r_bias = (const float*)d_in[7];   // [16,64]
    const float* ln1_g    = (const float*)d_in[8];
    const float* ln1_b    = (const float*)d_in[9];
    const float* ff_w1    = (const float*)d_in[10];  // [1024,4096]
    const float* ff_b1    = (const float*)d_in[11];
    const float* ff_w2    = (const float*)d_in[12];  // [4096,1024]
    const float* ff_b2    = (const float*)d_in[13];
    const float* ln2_g    = (const float*)d_in[14];
    const float* ln2_b    = (const float*)d_in[15];
    // d_in[16] = attn_mask: recomputed analytically (j > i + M), ignored.
    float* out = (float*)d_out;

    const dim3 t256(256);
    const int NOSPLIT = 1 << 30;

    // 1) w_heads = [mems; w] @ qkv_w             (C -> g_wheads, id 0)
    gemm_k<0, -1, 0, -1><<<dim3(24, 64), t256>>>(mems, w, MEMLEN * BSZ, qkv_w, 3072, 1024, nullptr, nullptr);
    // 2) r_head_k = r @ r_net_w                  (C -> g_rheadk, id 1)
    gemm_k<0, -1, 1, -1><<<dim3(8, 16), t256>>>(r, nullptr, NOSPLIT, r_net_w, 1024, 1024, nullptr, nullptr);
    // 3) masked relative-attention scores (AC + shifted BD)
    score_k<<<dim3(32, 16, 64), t256>>>(r_w_bias, r_r_bias);
    // 4) softmax over k
    softmax_k<<<64 * 1024, t256>>>();
    // 5) attn_vec = P @ V
    pv_k<<<dim3(16, 64), t256>>>();
    // 6) pre1 = w + attn_vec @ o_w               (A id 2, C id 3, resid = w)
    gemm_k<3, 2, 3, -1><<<dim3(8, 32), t256>>>(nullptr, nullptr, NOSPLIT, o_w, 1024, 1024, nullptr, w);
    // 7) out1 = LN1(pre1)
    ln_k<<<4096, t256>>>(nullptr, ln1_g, ln1_b);
    // 8) h = relu(out1 @ ff_w1 + b1)             (A id 4, C id 5)
    gemm_k<1, 4, 5, -1><<<dim3(32, 32), t256>>>(nullptr, nullptr, NOSPLIT, ff_w1, 4096, 1024, ff_b1, nullptr);
    // 9) pre2 = out1 + h @ ff_w2 + b2            (A id 5, C id 3, resid id 4)
    gemm_k<2, 5, 3, 4><<<dim3(8, 32), t256>>>(nullptr, nullptr, NOSPLIT, ff_w2, 1024, 4096, ff_b2, nullptr);
    // 10) out = LN2(pre2)
    ln_k<<<4096, t256>>>(out, ln2_g, ln2_b);
}

// round 4
// speedup vs baseline: 1.5036x; 1.5036x over previous
#include <cuda_runtime.h>
#include <math.h>
#include <stdint.h>

// ---------------- problem constants ----------------
#define QLEN   1024
#define BSZ    4
#define DMODEL 1024
#define NHEAD  16
#define DHEAD  64
#define DINNER 4096
#define MEMLEN 1024
#define KLEN   2048          // QLEN + MEMLEN
#define LN_EPS 1e-5f

// ---------------- scratch (device globals; no allocation allowed) ----------------
__device__ float g_wheads [(size_t)8192 * 3072];        // cat @ qkv_w   [row=j*B+b][3*1024]
__device__ float g_rheadk [(size_t)2048 * 1024];        // r @ r_net_w   [jj][n*64+d]
__device__ float g_scores [(size_t)64 * 1024 * 2048];   // [(b*16+n)][i][j]
__device__ float g_attnvec[(size_t)4096 * 1024];        // [i*B+b][n*64+d]
__device__ float g_pre    [(size_t)4096 * 1024];        // pre-layernorm buffer (reused)
__device__ float g_out1   [(size_t)4096 * 1024];        // LN1 output (also FFN residual)
__device__ float g_ffh    [(size_t)4096 * 4096];        // relu(out1@ff_w1+b1)

__device__ __forceinline__ float* gbuf(int id) {
    switch (id) {
        case 0: return g_wheads;
        case 1: return g_rheadk;
        case 2: return g_attnvec;
        case 3: return g_pre;
        case 4: return g_out1;
        case 5: return g_ffh;
    }
    return nullptr;
}

// ---------------- tf32 tensor-core helpers ----------------
__device__ __forceinline__ void mma_tf32(float (&d)[4], const uint32_t (&a)[4],
                                         uint32_t b0, uint32_t b1) {
    asm volatile(
        "mma.sync.aligned.m16n8k8.row.col.f32.tf32.tf32.f32 "
        "{%0,%1,%2,%3}, {%4,%5,%6,%7}, {%8,%9}, {%0,%1,%2,%3};"
        : "+f"(d[0]), "+f"(d[1]), "+f"(d[2]), "+f"(d[3])
        : "r"(a[0]), "r"(a[1]), "r"(a[2]), "r"(a[3]), "r"(b0), "r"(b1));
}

__device__ __forceinline__ void cp16(void* smem, const void* gmem) {
    uint32_t s = (uint32_t)__cvta_generic_to_shared(smem);
    asm volatile("cp.async.cg.shared.global [%0], [%1], 16;" :: "r"(s), "l"(gmem));
}

// ---------------- tf32 tensor-core GEMM ----------------
// C[Mr,Nc] = A[Mr,Kd] @ B[Kd,Nc]  (+ bias / relu / residual)
// 128x128 block, BK=16, 256 threads (8 warps: 4 along M x 2 along N),
// warp tile 32x64 = 2x8 m16n8k8 mma tiles. cp.async 2-stage pipeline.
// A rows gathered: row < Asplit -> A1, else A2 (for mems||w concat).
// EPI: 0 = plain, 1 = bias+relu, 2 = bias+resid, 3 = resid
// Padded smem strides: As stride 20 floats, Bs stride 136 floats — both make
// the mma fragment LDS.32 patterns hit 32 distinct banks (conflict-free).
template<int EPI, int AID, int CID, int RID>
__global__ __launch_bounds__(256)
void gemm_tc(const float* __restrict__ A1p, const float* __restrict__ A2p, int Asplit,
             const float* __restrict__ B, int Nc, int Kd,
             const float* __restrict__ bias, const float* __restrict__ residp)
{
    const float* A1 = (AID >= 0) ? gbuf(AID) : A1p;
    const float* A2 = A2p;
    float*       C  = gbuf(CID);
    const float* RS = (RID >= 0) ? gbuf(RID) : residp;

    __shared__ float As[2][128][20];     // [buf][m][k]  (k padded 16->20)
    __shared__ float Bs[2][16][136];     // [buf][k][n]  (n padded 128->136)

    const int tid  = threadIdx.x;
    const int lane = tid & 31, warp = tid >> 5;
    const int wm = warp & 3, wn = warp >> 2;      // 4 x 2 warp grid
    const int row0 = blockIdx.y * 128, col0 = blockIdx.x * 128;

    // global->shared load maps
    const int ar0 = tid >> 2, ac = (tid & 3) * 4;     // A: rows ar0, ar0+64; 16B chunk ac
    const int br0 = tid >> 5, bc = (tid & 31) * 4;    // B: rows br0, br0+8

    const int gra0 = row0 + ar0, gra1 = row0 + ar0 + 64;
    const float* arow0 = (gra0 < Asplit) ? A1 + (size_t)gra0 * Kd
                                         : A2 + (size_t)(gra0 - Asplit) * Kd;
    const float* arow1 = (gra1 < Asplit) ? A1 + (size_t)gra1 * Kd
                                         : A2 + (size_t)(gra1 - Asplit) * Kd;

    auto issue = [&](int kt, int buf) {
        const int k0 = kt * 16;
        cp16(&As[buf][ar0     ][ac], arow0 + k0 + ac);
        cp16(&As[buf][ar0 + 64][ac], arow1 + k0 + ac);
        cp16(&Bs[buf][br0    ][bc], B + (size_t)(k0 + br0    ) * Nc + col0 + bc);
        cp16(&Bs[buf][br0 + 8][bc], B + (size_t)(k0 + br0 + 8) * Nc + col0 + bc);
        asm volatile("cp.async.commit_group;");
    };

    float acc[2][8][4];
    #pragma unroll
    for (int mt = 0; mt < 2; mt++)
        #pragma unroll
        for (int nt = 0; nt < 8; nt++)
            #pragma unroll
            for (int e = 0; e < 4; e++) acc[mt][nt][e] = 0.f;

    const int r = lane >> 2, c = lane & 3;    // mma lane decomposition
    const int m0 = wm * 32, n0 = wn * 64;

    const int nK = Kd >> 4;
    issue(0, 0);

    for (int kt = 0; kt < nK; kt++) {
        const int buf = kt & 1;
        if (kt + 1 < nK) {
            issue(kt + 1, buf ^ 1);
            asm volatile("cp.async.wait_group 1;" ::: "memory");
        } else {
            asm volatile("cp.async.wait_group 0;" ::: "memory");
        }
        __syncthreads();

        const uint32_t* Ab = (const uint32_t*)&As[buf][0][0];
        const uint32_t* Bb = (const uint32_t*)&Bs[buf][0][0];
        #pragma unroll
        for (int ks = 0; ks < 2; ks++) {
            const int kb = ks * 8;
            uint32_t a[2][4];
            #pragma unroll
            for (int mt = 0; mt < 2; mt++) {
                const int mm = m0 + mt * 16;
                a[mt][0] = Ab[(mm + r    ) * 20 + kb + c];
                a[mt][1] = Ab[(mm + r + 8) * 20 + kb + c];
                a[mt][2] = Ab[(mm + r    ) * 20 + kb + c + 4];
                a[mt][3] = Ab[(mm + r + 8) * 20 + kb + c + 4];
            }
            #pragma unroll
            for (int nt = 0; nt < 8; nt++) {
                const int nn = n0 + nt * 8 + r;
                uint32_t b0 = Bb[(kb + c    ) * 136 + nn];
                uint32_t b1 = Bb[(kb + c + 4) * 136 + nn];
                mma_tf32(acc[0][nt], a[0], b0, b1);
                mma_tf32(acc[1][nt], a[1], b0, b1);
            }
        }
        __syncthreads();
    }

    // epilogue: thread holds rows (r, r+8) x cols (c*2, c*2+1) per mma tile
    #pragma unroll
    for (int mt = 0; mt < 2; mt++) {
        #pragma unroll
        for (int hh = 0; hh < 2; hh++) {
            const int gr = row0 + m0 + mt * 16 + r + hh * 8;
            float* crow = C + (size_t)gr * Nc;
            const float* rrow = (EPI == 2 || EPI == 3) ? RS + (size_t)gr * Nc : nullptr;
            #pragma unroll
            for (int nt = 0; nt < 8; nt++) {
                const int gc = col0 + n0 + nt * 8 + c * 2;
                float v0 = acc[mt][nt][hh * 2 + 0];
                float v1 = acc[mt][nt][hh * 2 + 1];
                if (EPI == 1 || EPI == 2) { v0 += bias[gc]; v1 += bias[gc + 1]; }
                if (EPI == 1) { v0 = fmaxf(v0, 0.f); v1 = fmaxf(v1, 0.f); }
                if (EPI == 2 || EPI == 3) { v0 += rrow[gc]; v1 += rrow[gc + 1]; }
                float2 o = make_float2(v0, v1);
                *(float2*)(crow + gc) = o;
            }
        }
    }
}

// ---------------- fused AC + BD score kernel ----------------
// score[i,j] = (q_i.k_j + rwb.k_j + q_i.r_d + rrb.r_d) * scale,  d = j - i + Q - 1
// masked (j > i+M) -> -1e30
__global__ __launch_bounds__(256)
void score_k(const float* __restrict__ rwbias, const float* __restrict__ rrbias)
{
    const int jt = blockIdx.x, it = blockIdx.y;
    const int n  = blockIdx.z & 15, b = blockIdx.z >> 4;
    const int i0 = it * 64, j0 = jt * 64;
    const int tid = threadIdx.x;
    float* out = g_scores + ((size_t)blockIdx.z * QLEN + i0) * KLEN + j0;

    if (j0 > i0 + 63 + MEMLEN) {            // fully masked tile: just fill
        #pragma unroll
        for (int e = 0; e < 16; e++) {
            int idx = e * 256 + tid;
            out[(size_t)(idx >> 6) * KLEN + (idx & 63)] = -1e30f;
        }
        return;
    }

    __shared__ __align__(16) float Qs[64][36];
    __shared__ __align__(16) float Ks[64][36];
    __shared__ __align__(16) float Rs[128][36];
    __shared__ float c1[64], c2[128], wb[64], rb[64];

    if (tid < 64)       wb[tid]      = rwbias[n * 64 + tid];
    else if (tid < 128) rb[tid - 64] = rrbias[n * 64 + tid - 64];

    const int ti4  = (tid >> 4) << 2;
    const int tj4  = (tid & 15) << 2;
    const int base = 63 + tj4 - ti4;                 // d - r_lo for (ii=jj=0)
    const int r_lo = (QLEN - 1) + j0 - i0 - 63;      // >= 0 always

    float ac[4][4] = {}, bd[4][4] = {};
    float c1r = 0.f, c2r = 0.f;

    for (int h = 0; h < 2; h++) {                    // K-dim halves of 32
        __syncthreads();
        #pragma unroll
        for (int l = 0; l < 2; l++) {
            int v = l * 256 + tid;
            int rr = v >> 3, c4 = v & 7;
            int qrow = (MEMLEN + i0 + rr) * BSZ + b;
            float4 fq = *(const float4*)(g_wheads + (size_t)qrow * 3072 + n * 64 + h * 32 + c4 * 4);
            *(float4*)&Qs[rr][c4 * 4] = fq;
            int krow = (j0 + rr) * BSZ + b;
            float4 fk = *(const float4*)(g_wheads + (size_t)krow * 3072 + 1024 + n * 64 + h * 32 + c4 * 4);
            *(float4*)&Ks[rr][c4 * 4] = fk;
        }
        #pragma unroll
        for (int l = 0; l < 4; l++) {
            int v = l * 256 + tid;
            int rr = v >> 3, c4 = v & 7;
            int grow = r_lo + rr; if (grow > KLEN - 1) grow = KLEN - 1;  // OOB rows only feed masked elems
            float4 fr = *(const float4*)(g_rheadk + (size_t)grow * 1024 + n * 64 + h * 32 + c4 * 4);
            *(float4*)&Rs[rr][c4 * 4] = fr;
        }
        __syncthreads();

        if (tid < 64) {
            #pragma unroll
            for (int kk = 0; kk < 32; kk++) c1r += wb[h * 32 + kk] * Ks[tid][kk];
        } else if (tid < 192) {
            #pragma unroll
            for (int kk = 0; kk < 32; kk++) c2r += rb[h * 32 + kk] * Rs[tid - 64][kk];
        }

        #pragma unroll
        for (int k4 = 0; k4 < 8; k4++) {
            float4 aa[4], kv[4], rv[7];
            #pragma unroll
            for (int ii = 0; ii < 4; ii++) aa[ii] = *(const float4*)&Qs[ti4 + ii][k4 * 4];
            #pragma unroll
            for (int jj = 0; jj < 4; jj++) kv[jj] = *(const float4*)&Ks[tj4 + jj][k4 * 4];
            #pragma unroll
            for (int s = 0; s < 7; s++)   rv[s] = *(const float4*)&Rs[base - 3 + s][k4 * 4];
            #pragma unroll
            for (int ii = 0; ii < 4; ii++)
                #pragma unroll
                for (int jj = 0; jj < 4; jj++) {
                    float4 a4 = aa[ii], k4v = kv[jj], r4 = rv[3 + jj - ii];
                    ac[ii][jj] += a4.x * k4v.x + a4.y * k4v.y + a4.z * k4v.z + a4.w * k4v.w;
                    bd[ii][jj] += a4.x * r4.x  + a4.y * r4.y  + a4.z * r4.z  + a4.w * r4.w;
                }
        }
    }

    if (tid < 64)       c1[tid]      = c1r;
    else if (tid < 192) c2[tid - 64] = c2r;
    __syncthreads();

    const float scale = 0.125f;   // 1/sqrt(64)
    #pragma unroll
    for (int ii = 0; ii < 4; ii++) {
        int i = i0 + ti4 + ii;
        #pragma unroll
        for (int jj = 0; jj < 4; jj++) {
            int j = j0 + tj4 + jj;
            float s = (ac[ii][jj] + bd[ii][jj] + c1[tj4 + jj] + c2[base + jj - ii]) * scale;
            if (j > i + MEMLEN) s = -1e30f;
            out[(size_t)(ti4 + ii) * KLEN + tj4 + jj] = s;
        }
    }
}

// ---------------- row softmax over KLEN=2048 ----------------
__global__ __launch_bounds__(256)
void softmax_k()
{
    float* row = g_scores + (size_t)blockIdx.x * KLEN;
    const int tid = threadIdx.x;
    float v[8];
    #pragma unroll
    for (int e = 0; e < 8; e++) v[e] = row[e * 256 + tid];

    float m = v[0];
    #pragma unroll
    for (int e = 1; e < 8; e++) m = fmaxf(m, v[e]);
    #pragma unroll
    for (int off = 16; off; off >>= 1) m = fmaxf(m, __shfl_xor_sync(0xffffffffu, m, off));
    __shared__ float sm[8], ss[8];
    if ((tid & 31) == 0) sm[tid >> 5] = m;
    __syncthreads();
    float M = sm[0];
    #pragma unroll
    for (int w = 1; w < 8; w++) M = fmaxf(M, sm[w]);

    float s = 0.f;
    #pragma unroll
    for (int e = 0; e < 8; e++) { v[e] = __expf(v[e] - M); s += v[e]; }
    #pragma unroll
    for (int off = 16; off; off >>= 1) s += __shfl_xor_sync(0xffffffffu, s, off);
    if ((tid & 31) == 0) ss[tid >> 5] = s;
    __syncthreads();
    float S = 0.f;
    #pragma unroll
    for (int w = 0; w < 8; w++) S += ss[w];
    float inv = 1.f / S;
    #pragma unroll
    for (int e = 0; e < 8; e++) row[e * 256 + tid] = v[e] * inv;
}

// ---------------- P @ V per (b, n) ----------------
__global__ __launch_bounds__(256, 2)
void pv_k()
{
    const int it = blockIdx.x;
    const int n  = blockIdx.y & 15, b = blockIdx.y >> 4;
    const int i0 = it * 64;
    const int tid = threadIdx.x;
    __shared__ __align__(16) float Ps [64][68];
    __shared__ __align__(16) float VsT[64][68];   // transposed: [d][j]
    const int ti4 = (tid >> 4) << 2;
    const int tj4 = (tid & 15) << 2;
    float acc[4][4] = {};

    const int jtiles = ((i0 + 63 + MEMLEN) >> 6) + 1;   // skip fully-masked (P==0) tiles
    const float* sc = g_scores + ((size_t)blockIdx.y * QLEN + i0) * KLEN;

    for (int jt = 0; jt < jtiles; jt++) {
        int j0 = jt * 64;
        __syncthreads();
        #pragma unroll
        for (int l = 0; l < 4; l++) {
            int v = l * 256 + tid;
            int rr = v >> 4, c4 = v & 15;
            float4 fp = *(const float4*)(sc + (size_t)rr * KLEN + j0 + c4 * 4);
            *(float4*)&Ps[rr][c4 * 4] = fp;
            float4 fv = *(const float4*)(g_wheads + (size_t)((j0 + rr) * BSZ + b) * 3072
                                         + 2048 + n * 64 + c4 * 4);
            VsT[c4 * 4 + 0][rr] = fv.x;
            VsT[c4 * 4 + 1][rr] = fv.y;
            VsT[c4 * 4 + 2][rr] = fv.z;
            VsT[c4 * 4 + 3][rr] = fv.w;
        }
        __syncthreads();
        #pragma unroll
        for (int k4 = 0; k4 < 16; k4++) {
            float4 aa[4], bb[4];
            #pragma unroll
            for (int ii = 0; ii < 4; ii++) aa[ii] = *(const float4*)&Ps[ti4 + ii][k4 * 4];
            #pragma unroll
            for (int jj = 0; jj < 4; jj++) bb[jj] = *(const float4*)&VsT[tj4 + jj][k4 * 4];
            #pragma unroll
            for (int ii = 0; ii < 4; ii++)
                #pragma unroll
                for (int jj = 0; jj < 4; jj++)
                    acc[ii][jj] += aa[ii].x * bb[jj].x + aa[ii].y * bb[jj].y
                                 + aa[ii].z * bb[jj].z + aa[ii].w * bb[jj].w;
        }
    }
    #pragma unroll
    for (int ii = 0; ii < 4; ii++)
        #pragma unroll
        for (int jj = 0; jj < 4; jj++)
            g_attnvec[(size_t)((i0 + ti4 + ii) * BSZ + b) * 1024 + n * 64 + tj4 + jj] = acc[ii][jj];
}

// ---------------- layernorm over D=1024 ----------------
__global__ __launch_bounds__(256)
void ln_k(float* __restrict__ yext, const float* __restrict__ gam, const float* __restrict__ bet)
{
    const float* row = g_pre + (size_t)blockIdx.x * DMODEL;
    float* orow = (yext ? yext : g_out1) + (size_t)blockIdx.x * DMODEL;
    const int tid = threadIdx.x;
    float v[4];
    float s = 0.f, sq = 0.f;
    #pragma unroll
    for (int e = 0; e < 4; e++) {
        v[e] = row[e * 256 + tid];
        s  += v[e];
        sq += v[e] * v[e];
    }
    #pragma unroll
    for (int off = 16; off; off >>= 1) {
        s  += __shfl_xor_sync(0xffffffffu, s,  off);
        sq += __shfl_xor_sync(0xffffffffu, sq, off);
    }
    __shared__ float sm[8], sm2[8];
    if ((tid & 31) == 0) { sm[tid >> 5] = s; sm2[tid >> 5] = sq; }
    __syncthreads();
    float S = 0.f, SQ = 0.f;
    #pragma unroll
    for (int w = 0; w < 8; w++) { S += sm[w]; SQ += sm2[w]; }
    const float mu  = S * (1.f / DMODEL);
    const float var = SQ * (1.f / DMODEL) - mu * mu;
    const float inv = rsqrtf(var + LN_EPS);
    #pragma unroll
    for (int e = 0; e < 4; e++) {
        int c = e * 256 + tid;
        orow[c] = (v[e] - mu) * inv * gam[c] + bet[c];
    }
}

// ---------------- launch ----------------
extern "C" void kernel_launch(void* const* d_in, const int* in_sizes, int n_in,
                              void* d_out, int out_size)
{
    const float* w        = (const float*)d_in[0];   // [1024,4,1024]
    const float* r        = (const float*)d_in[1];   // [2048,1,1024]
    const float* mems     = (const float*)d_in[2];   // [1024,4,1024]
    const float* qkv_w    = (const float*)d_in[3];   // [1024,3072]
    const float* r_net_w  = (const float*)d_in[4];   // [1024,1024]
    const float* o_w      = (const float*)d_in[5];   // [1024,1024]
    const float* r_w_bias = (const float*)d_in[6];   // [16,64]
    const float* r_r_bias = (const float*)d_in[7];   // [16,64]
    const float* ln1_g    = (const float*)d_in[8];
    const float* ln1_b    = (const float*)d_in[9];
    const float* ff_w1    = (const float*)d_in[10];  // [1024,4096]
    const float* ff_b1    = (const float*)d_in[11];
    const float* ff_w2    = (const float*)d_in[12];  // [4096,1024]
    const float* ff_b2    = (const float*)d_in[13];
    const float* ln2_g    = (const float*)d_in[14];
    const float* ln2_b    = (const float*)d_in[15];
    // d_in[16] = attn_mask: recomputed analytically (j > i + M), ignored.
    float* out = (float*)d_out;

    const dim3 t256(256);
    const int NOSPLIT = 1 << 30;

    // 1) w_heads = [mems; w] @ qkv_w             (C -> g_wheads, id 0)
    gemm_tc<0, -1, 0, -1><<<dim3(24, 64), t256>>>(mems, w, MEMLEN * BSZ, qkv_w, 3072, 1024, nullptr, nullptr);
    // 2) r_head_k = r @ r_net_w                  (C -> g_rheadk, id 1)
    gemm_tc<0, -1, 1, -1><<<dim3(8, 16), t256>>>(r, nullptr, NOSPLIT, r_net_w, 1024, 1024, nullptr, nullptr);
    // 3) masked relative-attention scores (AC + shifted BD)
    score_k<<<dim3(32, 16, 64), t256>>>(r_w_bias, r_r_bias);
    // 4) softmax over k
    softmax_k<<<64 * 1024, t256>>>();
    // 5) attn_vec = P @ V
    pv_k<<<dim3(16, 64), t256>>>();
    // 6) pre1 = w + attn_vec @ o_w               (A id 2, C id 3, resid = w)
    gemm_tc<3, 2, 3, -1><<<dim3(8, 32), t256>>>(nullptr, nullptr, NOSPLIT, o_w, 1024, 1024, nullptr, w);
    // 7) out1 = LN1(pre1)
    ln_k<<<4096, t256>>>(nullptr, ln1_g, ln1_b);
    // 8) h = relu(out1 @ ff_w1 + b1)             (A id 4, C id 5)
    gemm_tc<1, 4, 5, -1><<<dim3(32, 32), t256>>>(nullptr, nullptr, NOSPLIT, ff_w1, 4096, 1024, ff_b1, nullptr);
    // 9) pre2 = out1 + h @ ff_w2 + b2            (A id 5, C id 3, resid id 4)
    gemm_tc<2, 5, 3, 4><<<dim3(8, 32), t256>>>(nullptr, nullptr, NOSPLIT, ff_w2, 1024, 4096, ff_b2, nullptr);
    // 10) out = LN2(pre2)
    ln_k<<<4096, t256>>>(out, ln2_g, ln2_b);
}

// round 8
// speedup vs baseline: 3.5059x; 2.3317x over previous
#include <cuda_runtime.h>
#include <math.h>
#include <stdint.h>

// ---------------- problem constants ----------------
#define QLEN   1024
#define BSZ    4
#define DMODEL 1024
#define NHEAD  16
#define DHEAD  64
#define DINNER 4096
#define MEMLEN 1024
#define KLEN   2048          // QLEN + MEMLEN
#define LN_EPS 1e-5f

// ---------------- scratch (device globals; no allocation allowed) ----------------
__device__ float g_wheads [(size_t)8192 * 3072];        // cat @ qkv_w   [row=j*B+b][3*1024]
__device__ float g_rheadk [(size_t)2048 * 1024];        // r @ r_net_w   [jj][n*64+d]
__device__ float g_scores [(size_t)64 * 1024 * 2048];   // [(b*16+n)][i][j]
__device__ float g_attnvec[(size_t)4096 * 1024];        // [i*B+b][n*64+d]
__device__ float g_pre    [(size_t)4096 * 1024];        // pre-layernorm buffer (reused)
__device__ float g_out1   [(size_t)4096 * 1024];        // LN1 output (also FFN residual)
__device__ float g_ffh    [(size_t)4096 * 4096];        // relu(out1@ff_w1+b1)

__device__ __forceinline__ float* gbuf(int id) {
    switch (id) {
        case 0: return g_wheads;
        case 1: return g_rheadk;
        case 2: return g_attnvec;
        case 3: return g_pre;
        case 4: return g_out1;
        case 5: return g_ffh;
    }
    return nullptr;
}

// ---------------- tf32 tensor-core helpers ----------------
__device__ __forceinline__ void mma_tf32(float (&d)[4], const uint32_t (&a)[4],
                                         uint32_t b0, uint32_t b1) {
    asm volatile(
        "mma.sync.aligned.m16n8k8.row.col.f32.tf32.tf32.f32 "
        "{%0,%1,%2,%3}, {%4,%5,%6,%7}, {%8,%9}, {%0,%1,%2,%3};"
        : "+f"(d[0]), "+f"(d[1]), "+f"(d[2]), "+f"(d[3])
        : "r"(a[0]), "r"(a[1]), "r"(a[2]), "r"(a[3]), "r"(b0), "r"(b1));
}

__device__ __forceinline__ void cp16(void* smem, const void* gmem) {
    uint32_t s = (uint32_t)__cvta_generic_to_shared(smem);
    asm volatile("cp.async.cg.shared.global [%0], [%1], 16;" :: "r"(s), "l"(gmem));
}

__device__ __forceinline__ uint32_t tf32r(float f) {   // round-to-nearest tf32
    uint32_t u;
    asm("cvt.rna.tf32.f32 %0, %1;" : "=r"(u) : "f"(f));
    return u;
}

// ---------------- tf32 tensor-core GEMM (unchanged from passing R3) ----------------
template<int EPI, int AID, int CID, int RID>
__global__ __launch_bounds__(256)
void gemm_tc(const float* __restrict__ A1p, const float* __restrict__ A2p, int Asplit,
             const float* __restrict__ B, int Nc, int Kd,
             const float* __restrict__ bias, const float* __restrict__ residp)
{
    const float* A1 = (AID >= 0) ? gbuf(AID) : A1p;
    const float* A2 = A2p;
    float*       C  = gbuf(CID);
    const float* RS = (RID >= 0) ? gbuf(RID) : residp;

    __shared__ float As[2][128][20];
    __shared__ float Bs[2][16][136];

    const int tid  = threadIdx.x;
    const int lane = tid & 31, warp = tid >> 5;
    const int wm = warp & 3, wn = warp >> 2;
    const int row0 = blockIdx.y * 128, col0 = blockIdx.x * 128;

    const int ar0 = tid >> 2, ac = (tid & 3) * 4;
    const int br0 = tid >> 5, bc = (tid & 31) * 4;

    const int gra0 = row0 + ar0, gra1 = row0 + ar0 + 64;
    const float* arow0 = (gra0 < Asplit) ? A1 + (size_t)gra0 * Kd
                                         : A2 + (size_t)(gra0 - Asplit) * Kd;
    const float* arow1 = (gra1 < Asplit) ? A1 + (size_t)gra1 * Kd
                                         : A2 + (size_t)(gra1 - Asplit) * Kd;

    auto issue = [&](int kt, int buf) {
        const int k0 = kt * 16;
        cp16(&As[buf][ar0     ][ac], arow0 + k0 + ac);
        cp16(&As[buf][ar0 + 64][ac], arow1 + k0 + ac);
        cp16(&Bs[buf][br0    ][bc], B + (size_t)(k0 + br0    ) * Nc + col0 + bc);
        cp16(&Bs[buf][br0 + 8][bc], B + (size_t)(k0 + br0 + 8) * Nc + col0 + bc);
        asm volatile("cp.async.commit_group;");
    };

    float acc[2][8][4];
    #pragma unroll
    for (int mt = 0; mt < 2; mt++)
        #pragma unroll
        for (int nt = 0; nt < 8; nt++)
            #pragma unroll
            for (int e = 0; e < 4; e++) acc[mt][nt][e] = 0.f;

    const int r = lane >> 2, c = lane & 3;
    const int m0 = wm * 32, n0 = wn * 64;

    const int nK = Kd >> 4;
    issue(0, 0);

    for (int kt = 0; kt < nK; kt++) {
        const int buf = kt & 1;
        if (kt + 1 < nK) {
            issue(kt + 1, buf ^ 1);
            asm volatile("cp.async.wait_group 1;" ::: "memory");
        } else {
            asm volatile("cp.async.wait_group 0;" ::: "memory");
        }
        __syncthreads();

        const uint32_t* Ab = (const uint32_t*)&As[buf][0][0];
        const uint32_t* Bb = (const uint32_t*)&Bs[buf][0][0];
        #pragma unroll
        for (int ks = 0; ks < 2; ks++) {
            const int kb = ks * 8;
            uint32_t a[2][4];
            #pragma unroll
            for (int mt = 0; mt < 2; mt++) {
                const int mm = m0 + mt * 16;
                a[mt][0] = Ab[(mm + r    ) * 20 + kb + c];
                a[mt][1] = Ab[(mm + r + 8) * 20 + kb + c];
                a[mt][2] = Ab[(mm + r    ) * 20 + kb + c + 4];
                a[mt][3] = Ab[(mm + r + 8) * 20 + kb + c + 4];
            }
            #pragma unroll
            for (int nt = 0; nt < 8; nt++) {
                const int nn = n0 + nt * 8 + r;
                uint32_t b0 = Bb[(kb + c    ) * 136 + nn];
                uint32_t b1 = Bb[(kb + c + 4) * 136 + nn];
                mma_tf32(acc[0][nt], a[0], b0, b1);
                mma_tf32(acc[1][nt], a[1], b0, b1);
            }
        }
        __syncthreads();
    }

    #pragma unroll
    for (int mt = 0; mt < 2; mt++) {
        #pragma unroll
        for (int hh = 0; hh < 2; hh++) {
            const int gr = row0 + m0 + mt * 16 + r + hh * 8;
            float* crow = C + (size_t)gr * Nc;
            const float* rrow = (EPI == 2 || EPI == 3) ? RS + (size_t)gr * Nc : nullptr;
            #pragma unroll
            for (int nt = 0; nt < 8; nt++) {
                const int gc = col0 + n0 + nt * 8 + c * 2;
                float v0 = acc[mt][nt][hh * 2 + 0];
                float v1 = acc[mt][nt][hh * 2 + 1];
                if (EPI == 1 || EPI == 2) { v0 += bias[gc]; v1 += bias[gc + 1]; }
                if (EPI == 1) { v0 = fmaxf(v0, 0.f); v1 = fmaxf(v1, 0.f); }
                if (EPI == 2 || EPI == 3) { v0 += rrow[gc]; v1 += rrow[gc + 1]; }
                float2 o = make_float2(v0, v1);
                *(float2*)(crow + gc) = o;
            }
        }
    }
}

// ---------------- tensor-core relative-attention scores ----------------
// Per (b,n,i-tile of 64): loop 64-wide j-chunks.
//   AC  = (q + r_w_bias) . k_j             (bias folded into Q operand)
//   BD  = (q + r_r_bias) . r_{j-i+Q-1}     (bias via per-k delta on A fragment)
// BDwin (64 x 128 window) staged in smem, gathered along shifted diagonal.
// Dynamic smem: Qw[64][68], Ks[64][68], Rw[128][68], BDst[64][132], delta[64]
#define SC_SMEM_FLOATS (64*68 + 64*68 + 128*68 + 64*132 + 64)
__global__ __launch_bounds__(256)
void score_tc(const float* __restrict__ rwbias, const float* __restrict__ rrbias)
{
    extern __shared__ float smem[];
    float* Qw    = smem;                    // [64][68]
    float* Ks    = Qw + 64 * 68;            // [64][68]
    float* Rw    = Ks + 64 * 68;            // [128][68]
    float* BDst  = Rw + 128 * 68;           // [64][132]
    float* delta = BDst + 64 * 132;         // [64]

    const int it = blockIdx.x, bn = blockIdx.y;
    const int n = bn & 15, b = bn >> 4;
    const int i0 = it * 64;
    const int tid = threadIdx.x;
    const int lane = tid & 31, warp = tid >> 5;
    const int r = lane >> 2, c = lane & 3;
    const int m0  = (warp >> 1) * 16;        // i sub-tile
    const int n0a = (warp & 1) * 32;         // AC j half
    const int n0d = (warp & 1) * 64;         // BD d half

    const size_t sbase = ((size_t)bn * QLEN + i0) * KLEN;
    const int jtiles = ((i0 + 63 + MEMLEN) >> 6) + 1;

    // ---- load Qw = q + rwb ; delta = rrb - rwb ----
    {
        if (tid < 16) {
            float4 rw = *(const float4*)(rwbias + n * 64 + tid * 4);
            float4 rr = *(const float4*)(rrbias + n * 64 + tid * 4);
            delta[tid * 4 + 0] = rr.x - rw.x;
            delta[tid * 4 + 1] = rr.y - rw.y;
            delta[tid * 4 + 2] = rr.z - rw.z;
            delta[tid * 4 + 3] = rr.w - rw.w;
        }
        #pragma unroll
        for (int l = 0; l < 4; l++) {
            int v = l * 256 + tid;
            int rr = v >> 4, c4 = v & 15;
            float4 q = *(const float4*)(g_wheads
                        + (size_t)((MEMLEN + i0 + rr) * BSZ + b) * 3072 + n * 64 + c4 * 4);
            float4 rw = *(const float4*)(rwbias + n * 64 + c4 * 4);
            Qw[rr * 68 + c4 * 4 + 0] = q.x + rw.x;
            Qw[rr * 68 + c4 * 4 + 1] = q.y + rw.y;
            Qw[rr * 68 + c4 * 4 + 2] = q.z + rw.z;
            Qw[rr * 68 + c4 * 4 + 3] = q.w + rw.w;
        }
    }

    auto issue = [&](int jt) {
        const int j0c  = jt * 64;
        const int r_lo = (QLEN - 1) + j0c - i0 - 63;    // >= 0
        #pragma unroll
        for (int l = 0; l < 4; l++) {                   // K tile: 64 x 64
            int v = l * 256 + tid;
            int rr = v >> 4, c4 = v & 15;
            cp16(&Ks[rr * 68 + c4 * 4],
                 g_wheads + (size_t)((j0c + rr) * BSZ + b) * 3072 + 1024 + n * 64 + c4 * 4);
        }
        #pragma unroll
        for (int l = 0; l < 8; l++) {                   // R window: 128 x 64
            int v = l * 256 + tid;
            int rr = v >> 4, c4 = v & 15;
            int grow = r_lo + rr; if (grow > KLEN - 1) grow = KLEN - 1;  // masked later
            cp16(&Rw[rr * 68 + c4 * 4],
                 g_rheadk + (size_t)grow * 1024 + n * 64 + c4 * 4);
        }
        asm volatile("cp.async.commit_group;");
    };

    issue(0);

    for (int jt = 0; jt < jtiles; jt++) {
        const int j0c = jt * 64;
        asm volatile("cp.async.wait_group 0;" ::: "memory");
        __syncthreads();

        float accA[4][4], accB[8][4];
        #pragma unroll
        for (int nt = 0; nt < 4; nt++)
            #pragma unroll
            for (int e = 0; e < 4; e++) accA[nt][e] = 0.f;
        #pragma unroll
        for (int nt = 0; nt < 8; nt++)
            #pragma unroll
            for (int e = 0; e < 4; e++) accB[nt][e] = 0.f;

        #pragma unroll
        for (int ks = 0; ks < 8; ks++) {
            const int kb = ks * 8;
            float a0 = Qw[(m0 + r    ) * 68 + kb + c];
            float a1 = Qw[(m0 + r + 8) * 68 + kb + c];
            float a2 = Qw[(m0 + r    ) * 68 + kb + c + 4];
            float a3 = Qw[(m0 + r + 8) * 68 + kb + c + 4];
            float d0 = delta[kb + c], d1 = delta[kb + c + 4];
            uint32_t aw[4] = { tf32r(a0), tf32r(a1), tf32r(a2), tf32r(a3) };
            uint32_t ar[4] = { tf32r(a0 + d0), tf32r(a1 + d0),
                               tf32r(a2 + d1), tf32r(a3 + d1) };
            #pragma unroll
            for (int nt = 0; nt < 4; nt++) {
                int nn = n0a + nt * 8 + r;
                uint32_t b0 = tf32r(Ks[nn * 68 + kb + c]);
                uint32_t b1 = tf32r(Ks[nn * 68 + kb + c + 4]);
                mma_tf32(accA[nt], aw, b0, b1);
            }
            #pragma unroll
            for (int nt = 0; nt < 8; nt++) {
                int nn = n0d + nt * 8 + r;
                uint32_t b0 = tf32r(Rw[nn * 68 + kb + c]);
                uint32_t b1 = tf32r(Rw[nn * 68 + kb + c + 4]);
                mma_tf32(accB[nt], ar, b0, b1);
            }
        }

        __syncthreads();                       // Ks/Rw free now
        if (jt + 1 < jtiles) issue(jt + 1);    // overlap next loads with epilogue

        // stage BD window
        #pragma unroll
        for (int nt = 0; nt < 8; nt++) {
            int col = n0d + nt * 8 + 2 * c;
            BDst[(m0 + r    ) * 132 + col    ] = accB[nt][0];
            BDst[(m0 + r    ) * 132 + col + 1] = accB[nt][1];
            BDst[(m0 + r + 8) * 132 + col    ] = accB[nt][2];
            BDst[(m0 + r + 8) * 132 + col + 1] = accB[nt][3];
        }
        __syncthreads();

        // combine + mask + write
        #pragma unroll
        for (int nt = 0; nt < 4; nt++) {
            #pragma unroll
            for (int e = 0; e < 4; e++) {
                int ii  = m0 + r + ((e & 2) ? 8 : 0);
                int jjl = n0a + nt * 8 + 2 * c + (e & 1);
                float s = (accA[nt][e] + BDst[ii * 132 + (jjl - ii + 63)]) * 0.125f;
                if (j0c + jjl > i0 + ii + MEMLEN) s = -1e30f;
                g_scores[sbase + (size_t)ii * KLEN + j0c + jjl] = s;
            }
        }
    }

    // fill fully-masked tail tiles
    const int jfill0 = jtiles * 64;
    const int w4 = (KLEN - jfill0) >> 2;
    if (w4 > 0) {
        float4 neg = make_float4(-1e30f, -1e30f, -1e30f, -1e30f);
        for (int v = tid; v < 64 * w4; v += 256) {
            int rr = v / w4, cc = v - rr * w4;
            *(float4*)(g_scores + sbase + (size_t)rr * KLEN + jfill0 + cc * 4) = neg;
        }
    }
}

// ---------------- row softmax over KLEN=2048 ----------------
__global__ __launch_bounds__(256)
void softmax_k()
{
    float* row = g_scores + (size_t)blockIdx.x * KLEN;
    const int tid = threadIdx.x;
    float v[8];
    #pragma unroll
    for (int e = 0; e < 8; e++) v[e] = row[e * 256 + tid];

    float m = v[0];
    #pragma unroll
    for (int e = 1; e < 8; e++) m = fmaxf(m, v[e]);
    #pragma unroll
    for (int off = 16; off; off >>= 1) m = fmaxf(m, __shfl_xor_sync(0xffffffffu, m, off));
    __shared__ float sm[8], ss[8];
    if ((tid & 31) == 0) sm[tid >> 5] = m;
    __syncthreads();
    float M = sm[0];
    #pragma unroll
    for (int w = 1; w < 8; w++) M = fmaxf(M, sm[w]);

    float s = 0.f;
    #pragma unroll
    for (int e = 0; e < 8; e++) { v[e] = __expf(v[e] - M); s += v[e]; }
    #pragma unroll
    for (int off = 16; off; off >>= 1) s += __shfl_xor_sync(0xffffffffu, s, off);
    if ((tid & 31) == 0) ss[tid >> 5] = s;
    __syncthreads();
    float S = 0.f;
    #pragma unroll
    for (int w = 0; w < 8; w++) S += ss[w];
    float inv = 1.f / S;
    #pragma unroll
    for (int e = 0; e < 8; e++) row[e * 256 + tid] = v[e] * inv;
}

// ---------------- tensor-core P @ V ----------------
// Per (b,n,i-tile 64): A = P tile (64 x 64 from g_scores), B = V tile [j][d]
// (already [k][n] layout). Double-buffered cp.async.
// Dynamic smem: Ps[2][64][68], Vs[2][64][72]
#define PV_SMEM_FLOATS (2*64*68 + 2*64*72)
__global__ __launch_bounds__(256)
void pv_tc()
{
    extern __shared__ float smem[];
    float* Ps = smem;                 // [2][64][68]
    float* Vs = smem + 2 * 64 * 68;   // [2][64][72]

    const int it = blockIdx.x, bn = blockIdx.y;
    const int n = bn & 15, b = bn >> 4;
    const int i0 = it * 64;
    const int tid = threadIdx.x;
    const int lane = tid & 31, warp = tid >> 5;
    const int r = lane >> 2, c = lane & 3;
    const int m0 = (warp >> 1) * 16;
    const int n0 = (warp & 1) * 32;

    const size_t sbase = ((size_t)bn * QLEN + i0) * KLEN;
    const int jtiles = ((i0 + 63 + MEMLEN) >> 6) + 1;   // beyond: P == 0

    auto issue = [&](int jt, int buf) {
        const int j0 = jt * 64;
        #pragma unroll
        for (int l = 0; l < 4; l++) {
            int v = l * 256 + tid;
            int rr = v >> 4, c4 = v & 15;
            cp16(&Ps[(size_t)buf * 64 * 68 + rr * 68 + c4 * 4],
                 g_scores + sbase + (size_t)rr * KLEN + j0 + c4 * 4);
            cp16(&Vs[(size_t)buf * 64 * 72 + rr * 72 + c4 * 4],
                 g_wheads + (size_t)((j0 + rr) * BSZ + b) * 3072 + 2048 + n * 64 + c4 * 4);
        }
        asm volatile("cp.async.commit_group;");
    };

    float acc[4][4];
    #pragma unroll
    for (int nt = 0; nt < 4; nt++)
        #pragma unroll
        for (int e = 0; e < 4; e++) acc[nt][e] = 0.f;

    issue(0, 0);
    for (int jt = 0; jt < jtiles; jt++) {
        const int buf = jt & 1;
        if (jt + 1 < jtiles) {
            issue(jt + 1, buf ^ 1);
            asm volatile("cp.async.wait_group 1;" ::: "memory");
        } else {
            asm volatile("cp.async.wait_group 0;" ::: "memory");
        }
        __syncthreads();

        const float* Pb = Ps + (size_t)buf * 64 * 68;
        const float* Vb = Vs + (size_t)buf * 64 * 72;
        #pragma unroll
        for (int ks = 0; ks < 8; ks++) {
            const int kb = ks * 8;
            uint32_t a[4] = {
                tf32r(Pb[(m0 + r    ) * 68 + kb + c]),
                tf32r(Pb[(m0 + r + 8) * 68 + kb + c]),
                tf32r(Pb[(m0 + r    ) * 68 + kb + c + 4]),
                tf32r(Pb[(m0 + r + 8) * 68 + kb + c + 4]) };
            #pragma unroll
            for (int nt = 0; nt < 4; nt++) {
                int nn = n0 + nt * 8 + r;
                uint32_t b0 = tf32r(Vb[(kb + c    ) * 72 + nn]);
                uint32_t b1 = tf32r(Vb[(kb + c + 4) * 72 + nn]);
                mma_tf32(acc[nt], a, b0, b1);
            }
        }
        __syncthreads();
    }

    #pragma unroll
    for (int nt = 0; nt < 4; nt++) {
        const int dd = n0 + nt * 8 + 2 * c;
        const int row0 = i0 + m0 + r, row1 = row0 + 8;
        *(float2*)(g_attnvec + (size_t)(row0 * BSZ + b) * 1024 + n * 64 + dd)
            = make_float2(acc[nt][0], acc[nt][1]);
        *(float2*)(g_attnvec + (size_t)(row1 * BSZ + b) * 1024 + n * 64 + dd)
            = make_float2(acc[nt][2], acc[nt][3]);
    }
}

// ---------------- layernorm over D=1024 ----------------
__global__ __launch_bounds__(256)
void ln_k(float* __restrict__ yext, const float* __restrict__ gam, const float* __restrict__ bet)
{
    const float* row = g_pre + (size_t)blockIdx.x * DMODEL;
    float* orow = (yext ? yext : g_out1) + (size_t)blockIdx.x * DMODEL;
    const int tid = threadIdx.x;
    float v[4];
    float s = 0.f, sq = 0.f;
    #pragma unroll
    for (int e = 0; e < 4; e++) {
        v[e] = row[e * 256 + tid];
        s  += v[e];
        sq += v[e] * v[e];
    }
    #pragma unroll
    for (int off = 16; off; off >>= 1) {
        s  += __shfl_xor_sync(0xffffffffu, s,  off);
        sq += __shfl_xor_sync(0xffffffffu, sq, off);
    }
    __shared__ float sm[8], sm2[8];
    if ((tid & 31) == 0) { sm[tid >> 5] = s; sm2[tid >> 5] = sq; }
    __syncthreads();
    float S = 0.f, SQ = 0.f;
    #pragma unroll
    for (int w = 0; w < 8; w++) { S += sm[w]; SQ += sm2[w]; }
    const float mu  = S * (1.f / DMODEL);
    const float var = SQ * (1.f / DMODEL) - mu * mu;
    const float inv = rsqrtf(var + LN_EPS);
    #pragma unroll
    for (int e = 0; e < 4; e++) {
        int c = e * 256 + tid;
        orow[c] = (v[e] - mu) * inv * gam[c] + bet[c];
    }
}

// ---------------- launch ----------------
extern "C" void kernel_launch(void* const* d_in, const int* in_sizes, int n_in,
                              void* d_out, int out_size)
{
    const float* w        = (const float*)d_in[0];
    const float* r        = (const float*)d_in[1];
    const float* mems     = (const float*)d_in[2];
    const float* qkv_w    = (const float*)d_in[3];
    const float* r_net_w  = (const float*)d_in[4];
    const float* o_w      = (const float*)d_in[5];
    const float* r_w_bias = (const float*)d_in[6];
    const float* r_r_bias = (const float*)d_in[7];
    const float* ln1_g    = (const float*)d_in[8];
    const float* ln1_b    = (const float*)d_in[9];
    const float* ff_w1    = (const float*)d_in[10];
    const float* ff_b1    = (const float*)d_in[11];
    const float* ff_w2    = (const float*)d_in[12];
    const float* ff_b2    = (const float*)d_in[13];
    const float* ln2_g    = (const float*)d_in[14];
    const float* ln2_b    = (const float*)d_in[15];
    float* out = (float*)d_out;

    const dim3 t256(256);
    const int NOSPLIT = 1 << 30;

    static bool attr_done = false;
    if (!attr_done) {
        cudaFuncSetAttribute(score_tc, cudaFuncAttributeMaxDynamicSharedMemorySize,
                             SC_SMEM_FLOATS * 4);
        cudaFuncSetAttribute(pv_tc, cudaFuncAttributeMaxDynamicSharedMemorySize,
                             PV_SMEM_FLOATS * 4);
        attr_done = true;
    }

    // 1) w_heads = [mems; w] @ qkv_w
    gemm_tc<0, -1, 0, -1><<<dim3(24, 64), t256>>>(mems, w, MEMLEN * BSZ, qkv_w, 3072, 1024, nullptr, nullptr);
    // 2) r_head_k = r @ r_net_w
    gemm_tc<0, -1, 1, -1><<<dim3(8, 16), t256>>>(r, nullptr, NOSPLIT, r_net_w, 1024, 1024, nullptr, nullptr);
    // 3) masked relative-attention scores (tensorized AC + shifted BD)
    score_tc<<<dim3(16, 64), t256, SC_SMEM_FLOATS * 4>>>(r_w_bias, r_r_bias);
    // 4) softmax over k
    softmax_k<<<64 * 1024, t256>>>();
    // 5) attn_vec = P @ V (tensorized)
    pv_tc<<<dim3(16, 64), t256, PV_SMEM_FLOATS * 4>>>();
    // 6) pre1 = w + attn_vec @ o_w
    gemm_tc<3, 2, 3, -1><<<dim3(8, 32), t256>>>(nullptr, nullptr, NOSPLIT, o_w, 1024, 1024, nullptr, w);
    // 7) out1 = LN1(pre1)
    ln_k<<<4096, t256>>>(nullptr, ln1_g, ln1_b);
    // 8) h = relu(out1 @ ff_w1 + b1)
    gemm_tc<1, 4, 5, -1><<<dim3(32, 32), t256>>>(nullptr, nullptr, NOSPLIT, ff_w1, 4096, 1024, ff_b1, nullptr);
    // 9) pre2 = out1 + h @ ff_w2 + b2
    gemm_tc<2, 5, 3, 4><<<dim3(8, 32), t256>>>(nullptr, nullptr, NOSPLIT, ff_w2, 1024, 4096, ff_b2, nullptr);
    // 10) out = LN2(pre2)
    ln_k<<<4096, t256>>>(out, ln2_g, ln2_b);
}

// round 12
// speedup vs baseline: 3.8815x; 1.1071x over previous
#include <cuda_runtime.h>
#include <math.h>
#include <stdint.h>

// ---------------- problem constants ----------------
#define QLEN   1024
#define BSZ    4
#define DMODEL 1024
#define NHEAD  16
#define DHEAD  64
#define DINNER 4096
#define MEMLEN 1024
#define KLEN   2048          // QLEN + MEMLEN
#define LN_EPS 1e-5f

// ---------------- scratch (device globals; no allocation allowed) ----------------
__device__ float g_wheads [(size_t)8192 * 3072];        // cat @ qkv_w   [row=j*B+b][3*1024]
__device__ float g_rheadk [(size_t)2048 * 1024];        // r @ r_net_w   [jj][n*64+d]
__device__ float g_attnvec[(size_t)4096 * 1024];        // [i*B+b][n*64+d]
__device__ float g_pre    [(size_t)4096 * 1024];        // pre-layernorm buffer (reused)
__device__ float g_out1   [(size_t)4096 * 1024];        // LN1 output (also FFN residual)
__device__ float g_ffh    [(size_t)4096 * 4096];        // relu(out1@ff_w1+b1)

__device__ __forceinline__ float* gbuf(int id) {
    switch (id) {
        case 0: return g_wheads;
        case 1: return g_rheadk;
        case 2: return g_attnvec;
        case 3: return g_pre;
        case 4: return g_out1;
        case 5: return g_ffh;
    }
    return nullptr;
}

// ---------------- tf32 tensor-core helpers ----------------
__device__ __forceinline__ void mma_tf32(float (&d)[4], const uint32_t (&a)[4],
                                         uint32_t b0, uint32_t b1) {
    asm volatile(
        "mma.sync.aligned.m16n8k8.row.col.f32.tf32.tf32.f32 "
        "{%0,%1,%2,%3}, {%4,%5,%6,%7}, {%8,%9}, {%0,%1,%2,%3};"
        : "+f"(d[0]), "+f"(d[1]), "+f"(d[2]), "+f"(d[3])
        : "r"(a[0]), "r"(a[1]), "r"(a[2]), "r"(a[3]), "r"(b0), "r"(b1));
}

__device__ __forceinline__ void cp16(void* smem, const void* gmem) {
    uint32_t s = (uint32_t)__cvta_generic_to_shared(smem);
    asm volatile("cp.async.cg.shared.global [%0], [%1], 16;" :: "r"(s), "l"(gmem));
}

__device__ __forceinline__ uint32_t tf32r(float f) {   // round-to-nearest tf32
    uint32_t u;
    asm("cvt.rna.tf32.f32 %0, %1;" : "=r"(u) : "f"(f));
    return u;
}

// ---------------- tf32 tensor-core GEMM (unchanged, proven) ----------------
template<int EPI, int AID, int CID, int RID>
__global__ __launch_bounds__(256)
void gemm_tc(const float* __restrict__ A1p, const float* __restrict__ A2p, int Asplit,
             const float* __restrict__ B, int Nc, int Kd,
             const float* __restrict__ bias, const float* __restrict__ residp)
{
    const float* A1 = (AID >= 0) ? gbuf(AID) : A1p;
    const float* A2 = A2p;
    float*       C  = gbuf(CID);
    const float* RS = (RID >= 0) ? gbuf(RID) : residp;

    __shared__ float As[2][128][20];
    __shared__ float Bs[2][16][136];

    const int tid  = threadIdx.x;
    const int lane = tid & 31, warp = tid >> 5;
    const int wm = warp & 3, wn = warp >> 2;
    const int row0 = blockIdx.y * 128, col0 = blockIdx.x * 128;

    const int ar0 = tid >> 2, ac = (tid & 3) * 4;
    const int br0 = tid >> 5, bc = (tid & 31) * 4;

    const int gra0 = row0 + ar0, gra1 = row0 + ar0 + 64;
    const float* arow0 = (gra0 < Asplit) ? A1 + (size_t)gra0 * Kd
                                         : A2 + (size_t)(gra0 - Asplit) * Kd;
    const float* arow1 = (gra1 < Asplit) ? A1 + (size_t)gra1 * Kd
                                         : A2 + (size_t)(gra1 - Asplit) * Kd;

    auto issue = [&](int kt, int buf) {
        const int k0 = kt * 16;
        cp16(&As[buf][ar0     ][ac], arow0 + k0 + ac);
        cp16(&As[buf][ar0 + 64][ac], arow1 + k0 + ac);
        cp16(&Bs[buf][br0    ][bc], B + (size_t)(k0 + br0    ) * Nc + col0 + bc);
        cp16(&Bs[buf][br0 + 8][bc], B + (size_t)(k0 + br0 + 8) * Nc + col0 + bc);
        asm volatile("cp.async.commit_group;");
    };

    float acc[2][8][4];
    #pragma unroll
    for (int mt = 0; mt < 2; mt++)
        #pragma unroll
        for (int nt = 0; nt < 8; nt++)
            #pragma unroll
            for (int e = 0; e < 4; e++) acc[mt][nt][e] = 0.f;

    const int r = lane >> 2, c = lane & 3;
    const int m0 = wm * 32, n0 = wn * 64;

    const int nK = Kd >> 4;
    issue(0, 0);

    for (int kt = 0; kt < nK; kt++) {
        const int buf = kt & 1;
        if (kt + 1 < nK) {
            issue(kt + 1, buf ^ 1);
            asm volatile("cp.async.wait_group 1;" ::: "memory");
        } else {
            asm volatile("cp.async.wait_group 0;" ::: "memory");
        }
        __syncthreads();

        const uint32_t* Ab = (const uint32_t*)&As[buf][0][0];
        const uint32_t* Bb = (const uint32_t*)&Bs[buf][0][0];
        #pragma unroll
        for (int ks = 0; ks < 2; ks++) {
            const int kb = ks * 8;
            uint32_t a[2][4];
            #pragma unroll
            for (int mt = 0; mt < 2; mt++) {
                const int mm = m0 + mt * 16;
                a[mt][0] = Ab[(mm + r    ) * 20 + kb + c];
                a[mt][1] = Ab[(mm + r + 8) * 20 + kb + c];
                a[mt][2] = Ab[(mm + r    ) * 20 + kb + c + 4];
                a[mt][3] = Ab[(mm + r + 8) * 20 + kb + c + 4];
            }
            #pragma unroll
            for (int nt = 0; nt < 8; nt++) {
                const int nn = n0 + nt * 8 + r;
                uint32_t b0 = Bb[(kb + c    ) * 136 + nn];
                uint32_t b1 = Bb[(kb + c + 4) * 136 + nn];
                mma_tf32(acc[0][nt], a[0], b0, b1);
                mma_tf32(acc[1][nt], a[1], b0, b1);
            }
        }
        __syncthreads();
    }

    #pragma unroll
    for (int mt = 0; mt < 2; mt++) {
        #pragma unroll
        for (int hh = 0; hh < 2; hh++) {
            const int gr = row0 + m0 + mt * 16 + r + hh * 8;
            float* crow = C + (size_t)gr * Nc;
            const float* rrow = (EPI == 2 || EPI == 3) ? RS + (size_t)gr * Nc : nullptr;
            #pragma unroll
            for (int nt = 0; nt < 8; nt++) {
                const int gc = col0 + n0 + nt * 8 + c * 2;
                float v0 = acc[mt][nt][hh * 2 + 0];
                float v1 = acc[mt][nt][hh * 2 + 1];
                if (EPI == 1 || EPI == 2) { v0 += bias[gc]; v1 += bias[gc + 1]; }
                if (EPI == 1) { v0 = fmaxf(v0, 0.f); v1 = fmaxf(v1, 0.f); }
                if (EPI == 2 || EPI == 3) { v0 += rrow[gc]; v1 += rrow[gc + 1]; }
                float2 o = make_float2(v0, v1);
                *(float2*)(crow + gc) = o;
            }
        }
    }
}

// ---------------- fused flash attention: scores + online softmax + P@V ----------
// Per (b,n,i-tile of 64): loop 64-wide j-chunks.
//   AC = (q + r_w_bias).k_j ; BD = (q + r_r_bias).r_{j-i+Q-1} via 128-wide window
//   s = (AC + BD_gather)*scale, masked; staged in smem Pst (never hits gmem).
//   Online softmax (running M, l; rescale O by exp(M_old-M_new)); P@V via tf32 mma.
// Dyn smem: Qw[64][68], delta[64], Ks[64][68], Rw[128][68], Vs[2][64][72],
//           BDst[64][132], Pst[64][68]
#define AF_SMEM_FLOATS (64*68 + 64 + 64*68 + 128*68 + 2*64*72 + 64*132 + 64*68)
__global__ __launch_bounds__(256)
void attn_flash(const float* __restrict__ rwbias, const float* __restrict__ rrbias)
{
    extern __shared__ float smem[];
    float* Qw    = smem;                    // [64][68]
    float* delta = Qw + 64 * 68;            // [64]
    float* Ks    = delta + 64;              // [64][68]
    float* Rw    = Ks + 64 * 68;            // [128][68]
    float* Vs    = Rw + 128 * 68;           // [2][64][72]
    float* BDst  = Vs + 2 * 64 * 72;        // [64][132]
    float* Pst   = BDst + 64 * 132;         // [64][68]

    const int it = blockIdx.x, bn = blockIdx.y;
    const int n = bn & 15, b = bn >> 4;
    const int i0 = it * 64;
    const int tid = threadIdx.x;
    const int lane = tid & 31, warp = tid >> 5;
    const int r = lane >> 2, c = lane & 3;
    const int m0  = (warp >> 1) * 16;        // i sub-tile (16 rows)
    const int half = warp & 1;
    const int n0a = half * 32;               // AC j half
    const int n0d = half * 64;               // BD d half
    const int n0v = half * 32;               // PV output-d half

    const int jtiles = ((i0 + 63 + MEMLEN) >> 6) + 1;

    // ---- load Qw = q + rwb ; delta = rrb - rwb ----
    if (tid < 16) {
        float4 rw = *(const float4*)(rwbias + n * 64 + tid * 4);
        float4 rr = *(const float4*)(rrbias + n * 64 + tid * 4);
        delta[tid * 4 + 0] = rr.x - rw.x;
        delta[tid * 4 + 1] = rr.y - rw.y;
        delta[tid * 4 + 2] = rr.z - rw.z;
        delta[tid * 4 + 3] = rr.w - rw.w;
    }
    #pragma unroll
    for (int l = 0; l < 4; l++) {
        int v = l * 256 + tid;
        int rr = v >> 4, c4 = v & 15;
        float4 q = *(const float4*)(g_wheads
                    + (size_t)((MEMLEN + i0 + rr) * BSZ + b) * 3072 + n * 64 + c4 * 4);
        float4 rw = *(const float4*)(rwbias + n * 64 + c4 * 4);
        Qw[rr * 68 + c4 * 4 + 0] = q.x + rw.x;
        Qw[rr * 68 + c4 * 4 + 1] = q.y + rw.y;
        Qw[rr * 68 + c4 * 4 + 2] = q.z + rw.z;
        Qw[rr * 68 + c4 * 4 + 3] = q.w + rw.w;
    }

    auto issue = [&](int jt, int vbuf) {
        const int j0c  = jt * 64;
        const int r_lo = (QLEN - 1) + j0c - i0 - 63;    // >= 0
        #pragma unroll
        for (int l = 0; l < 4; l++) {                   // K tile 64x64
            int v = l * 256 + tid;
            int rr = v >> 4, c4 = v & 15;
            cp16(&Ks[rr * 68 + c4 * 4],
                 g_wheads + (size_t)((j0c + rr) * BSZ + b) * 3072 + 1024 + n * 64 + c4 * 4);
        }
        #pragma unroll
        for (int l = 0; l < 8; l++) {                   // R window 128x64
            int v = l * 256 + tid;
            int rr = v >> 4, c4 = v & 15;
            int grow = r_lo + rr; if (grow > KLEN - 1) grow = KLEN - 1;  // feeds masked only
            cp16(&Rw[rr * 68 + c4 * 4],
                 g_rheadk + (size_t)grow * 1024 + n * 64 + c4 * 4);
        }
        #pragma unroll
        for (int l = 0; l < 4; l++) {                   // V tile 64x64 (double-buffered)
            int v = l * 256 + tid;
            int rr = v >> 4, c4 = v & 15;
            cp16(&Vs[(size_t)vbuf * 64 * 72 + rr * 72 + c4 * 4],
                 g_wheads + (size_t)((j0c + rr) * BSZ + b) * 3072 + 2048 + n * 64 + c4 * 4);
        }
        asm volatile("cp.async.commit_group;");
    };

    // persistent state
    float accO[4][4];
    #pragma unroll
    for (int nt = 0; nt < 4; nt++)
        #pragma unroll
        for (int e = 0; e < 4; e++) accO[nt][e] = 0.f;
    float M0 = -1e30f, M1 = -1e30f, l0 = 0.f, l1 = 0.f;

    issue(0, 0);

    for (int jt = 0; jt < jtiles; jt++) {
        const int j0c = jt * 64;
        const int vbuf = jt & 1;
        asm volatile("cp.async.wait_group 0;" ::: "memory");
        __syncthreads();

        // ---- score phase: AC + BD mma (identical math to proven score_tc) ----
        float accA[4][4], accB[8][4];
        #pragma unroll
        for (int nt = 0; nt < 4; nt++)
            #pragma unroll
            for (int e = 0; e < 4; e++) accA[nt][e] = 0.f;
        #pragma unroll
        for (int nt = 0; nt < 8; nt++)
            #pragma unroll
            for (int e = 0; e < 4; e++) accB[nt][e] = 0.f;

        #pragma unroll
        for (int ks = 0; ks < 8; ks++) {
            const int kb = ks * 8;
            float a0 = Qw[(m0 + r    ) * 68 + kb + c];
            float a1 = Qw[(m0 + r + 8) * 68 + kb + c];
            float a2 = Qw[(m0 + r    ) * 68 + kb + c + 4];
            float a3 = Qw[(m0 + r + 8) * 68 + kb + c + 4];
            float d0 = delta[kb + c], d1 = delta[kb + c + 4];
            uint32_t aw[4] = { tf32r(a0), tf32r(a1), tf32r(a2), tf32r(a3) };
            uint32_t ar[4] = { tf32r(a0 + d0), tf32r(a1 + d0),
                               tf32r(a2 + d1), tf32r(a3 + d1) };
            #pragma unroll
            for (int nt = 0; nt < 4; nt++) {
                int nn = n0a + nt * 8 + r;
                uint32_t b0 = tf32r(Ks[nn * 68 + kb + c]);
                uint32_t b1 = tf32r(Ks[nn * 68 + kb + c + 4]);
                mma_tf32(accA[nt], aw, b0, b1);
            }
            #pragma unroll
            for (int nt = 0; nt < 8; nt++) {
                int nn = n0d + nt * 8 + r;
                uint32_t b0 = tf32r(Rw[nn * 68 + kb + c]);
                uint32_t b1 = tf32r(Rw[nn * 68 + kb + c + 4]);
                mma_tf32(accB[nt], ar, b0, b1);
            }
        }

        __syncthreads();                       // Ks/Rw reads done
        if (jt + 1 < jtiles) issue(jt + 1, vbuf ^ 1);   // overlap with rest of chunk

        // ---- stage BD window ----
        #pragma unroll
        for (int nt = 0; nt < 8; nt++) {
            int col = n0d + nt * 8 + 2 * c;
            BDst[(m0 + r    ) * 132 + col    ] = accB[nt][0];
            BDst[(m0 + r    ) * 132 + col + 1] = accB[nt][1];
            BDst[(m0 + r + 8) * 132 + col    ] = accB[nt][2];
            BDst[(m0 + r + 8) * 132 + col + 1] = accB[nt][3];
        }
        __syncthreads();

        // ---- combine + mask -> Pst (smem, not gmem) ----
        #pragma unroll
        for (int nt = 0; nt < 4; nt++) {
            #pragma unroll
            for (int e = 0; e < 4; e++) {
                int ii  = m0 + r + ((e & 2) ? 8 : 0);
                int jjl = n0a + nt * 8 + 2 * c + (e & 1);
                float s = (accA[nt][e] + BDst[ii * 132 + (jjl - ii + 63)]) * 0.125f;
                if (j0c + jjl > i0 + ii + MEMLEN) s = -1e30f;
                Pst[ii * 68 + jjl] = s;
            }
        }
        __syncthreads();

        // ---- online softmax update ----
        float cm0 = -1e30f, cm1 = -1e30f;
        #pragma unroll
        for (int ks = 0; ks < 8; ks++) {
            const int kb = ks * 8;
            cm0 = fmaxf(cm0, fmaxf(Pst[(m0 + r    ) * 68 + kb + c],
                                   Pst[(m0 + r    ) * 68 + kb + c + 4]));
            cm1 = fmaxf(cm1, fmaxf(Pst[(m0 + r + 8) * 68 + kb + c],
                                   Pst[(m0 + r + 8) * 68 + kb + c + 4]));
        }
        cm0 = fmaxf(cm0, __shfl_xor_sync(0xffffffffu, cm0, 1));
        cm0 = fmaxf(cm0, __shfl_xor_sync(0xffffffffu, cm0, 2));
        cm1 = fmaxf(cm1, __shfl_xor_sync(0xffffffffu, cm1, 1));
        cm1 = fmaxf(cm1, __shfl_xor_sync(0xffffffffu, cm1, 2));
        const float M0n = fmaxf(M0, cm0), M1n = fmaxf(M1, cm1);
        const float f0 = __expf(M0 - M0n), f1 = __expf(M1 - M1n);
        M0 = M0n; M1 = M1n;
        l0 *= f0; l1 *= f1;
        #pragma unroll
        for (int nt = 0; nt < 4; nt++) {
            accO[nt][0] *= f0; accO[nt][1] *= f0;
            accO[nt][2] *= f1; accO[nt][3] *= f1;
        }

        // ---- P = exp(s - M), accumulate l, P@V mma ----
        const float* Vb = Vs + (size_t)vbuf * 64 * 72;
        #pragma unroll
        for (int ks = 0; ks < 8; ks++) {
            const int kb = ks * 8;
            float p0 = __expf(Pst[(m0 + r    ) * 68 + kb + c    ] - M0);
            float p1 = __expf(Pst[(m0 + r + 8) * 68 + kb + c    ] - M1);
            float p2 = __expf(Pst[(m0 + r    ) * 68 + kb + c + 4] - M0);
            float p3 = __expf(Pst[(m0 + r + 8) * 68 + kb + c + 4] - M1);
            l0 += p0 + p2;
            l1 += p1 + p3;
            uint32_t a[4] = { tf32r(p0), tf32r(p1), tf32r(p2), tf32r(p3) };
            #pragma unroll
            for (int nt = 0; nt < 4; nt++) {
                int nn = n0v + nt * 8 + r;
                uint32_t b0 = tf32r(Vb[(kb + c    ) * 72 + nn]);
                uint32_t b1 = tf32r(Vb[(kb + c + 4) * 72 + nn]);
                mma_tf32(accO[nt], a, b0, b1);
            }
        }
        __syncthreads();   // Pst/BDst reuse next chunk
    }

    // ---- finalize: normalize and write ----
    l0 += __shfl_xor_sync(0xffffffffu, l0, 1);
    l0 += __shfl_xor_sync(0xffffffffu, l0, 2);
    l1 += __shfl_xor_sync(0xffffffffu, l1, 1);
    l1 += __shfl_xor_sync(0xffffffffu, l1, 2);
    const float inv0 = 1.f / l0, inv1 = 1.f / l1;
    #pragma unroll
    for (int nt = 0; nt < 4; nt++) {
        const int dd = n0v + nt * 8 + 2 * c;
        const int row0 = i0 + m0 + r, row1 = row0 + 8;
        *(float2*)(g_attnvec + (size_t)(row0 * BSZ + b) * 1024 + n * 64 + dd)
            = make_float2(accO[nt][0] * inv0, accO[nt][1] * inv0);
        *(float2*)(g_attnvec + (size_t)(row1 * BSZ + b) * 1024 + n * 64 + dd)
            = make_float2(accO[nt][2] * inv1, accO[nt][3] * inv1);
    }
}

// ---------------- layernorm over D=1024 ----------------
__global__ __launch_bounds__(256)
void ln_k(float* __restrict__ yext, const float* __restrict__ gam, const float* __restrict__ bet)
{
    const float* row = g_pre + (size_t)blockIdx.x * DMODEL;
    float* orow = (yext ? yext : g_out1) + (size_t)blockIdx.x * DMODEL;
    const int tid = threadIdx.x;
    float v[4];
    float s = 0.f, sq = 0.f;
    #pragma unroll
    for (int e = 0; e < 4; e++) {
        v[e] = row[e * 256 + tid];
        s  += v[e];
        sq += v[e] * v[e];
    }
    #pragma unroll
    for (int off = 16; off; off >>= 1) {
        s  += __shfl_xor_sync(0xffffffffu, s,  off);
        sq += __shfl_xor_sync(0xffffffffu, sq, off);
    }
    __shared__ float sm[8], sm2[8];
    if ((tid & 31) == 0) { sm[tid >> 5] = s; sm2[tid >> 5] = sq; }
    __syncthreads();
    float S = 0.f, SQ = 0.f;
    #pragma unroll
    for (int w = 0; w < 8; w++) { S += sm[w]; SQ += sm2[w]; }
    const float mu  = S * (1.f / DMODEL);
    const float var = SQ * (1.f / DMODEL) - mu * mu;
    const float inv = rsqrtf(var + LN_EPS);
    #pragma unroll
    for (int e = 0; e < 4; e++) {
        int c = e * 256 + tid;
        orow[c] = (v[e] - mu) * inv * gam[c] + bet[c];
    }
}

// ---------------- launch ----------------
extern "C" void kernel_launch(void* const* d_in, const int* in_sizes, int n_in,
                              void* d_out, int out_size)
{
    const float* w        = (const float*)d_in[0];
    const float* r        = (const float*)d_in[1];
    const float* mems     = (const float*)d_in[2];
    const float* qkv_w    = (const float*)d_in[3];
    const float* r_net_w  = (const float*)d_in[4];
    const float* o_w      = (const float*)d_in[5];
    const float* r_w_bias = (const float*)d_in[6];
    const float* r_r_bias = (const float*)d_in[7];
    const float* ln1_g    = (const float*)d_in[8];
    const float* ln1_b    = (const float*)d_in[9];
    const float* ff_w1    = (const float*)d_in[10];
    const float* ff_b1    = (const float*)d_in[11];
    const float* ff_w2    = (const float*)d_in[12];
    const float* ff_b2    = (const float*)d_in[13];
    const float* ln2_g    = (const float*)d_in[14];
    const float* ln2_b    = (const float*)d_in[15];
    float* out = (float*)d_out;

    const dim3 t256(256);
    const int NOSPLIT = 1 << 30;

    static bool attr_done = false;
    if (!attr_done) {
        cudaFuncSetAttribute(attn_flash, cudaFuncAttributeMaxDynamicSharedMemorySize,
                             AF_SMEM_FLOATS * 4);
        attr_done = true;
    }

    // 1) w_heads = [mems; w] @ qkv_w
    gemm_tc<0, -1, 0, -1><<<dim3(24, 64), t256>>>(mems, w, MEMLEN * BSZ, qkv_w, 3072, 1024, nullptr, nullptr);
    // 2) r_head_k = r @ r_net_w
    gemm_tc<0, -1, 1, -1><<<dim3(8, 16), t256>>>(r, nullptr, NOSPLIT, r_net_w, 1024, 1024, nullptr, nullptr);
    // 3) fused: scores + online softmax + P@V  -> g_attnvec
    attn_flash<<<dim3(16, 64), t256, AF_SMEM_FLOATS * 4>>>(r_w_bias, r_r_bias);
    // 4) pre1 = w + attn_vec @ o_w
    gemm_tc<3, 2, 3, -1><<<dim3(8, 32), t256>>>(nullptr, nullptr, NOSPLIT, o_w, 1024, 1024, nullptr, w);
    // 5) out1 = LN1(pre1)
    ln_k<<<4096, t256>>>(nullptr, ln1_g, ln1_b);
    // 6) h = relu(out1 @ ff_w1 + b1)
    gemm_tc<1, 4, 5, -1><<<dim3(32, 32), t256>>>(nullptr, nullptr, NOSPLIT, ff_w1, 4096, 1024, ff_b1, nullptr);
    // 7) pre2 = out1 + h @ ff_w2 + b2
    gemm_tc<2, 5, 3, 4><<<dim3(8, 32), t256>>>(nullptr, nullptr, NOSPLIT, ff_w2, 1024, 4096, ff_b2, nullptr);
    // 8) out = LN2(pre2)
    ln_k<<<4096, t256>>>(out, ln2_g, ln2_b);
}

// round 16
// speedup vs baseline: 4.1590x; 1.0715x over previous
#include <cuda_runtime.h>
#include <math.h>
#include <stdint.h>

// ---------------- problem constants ----------------
#define QLEN   1024
#define BSZ    4
#define DMODEL 1024
#define NHEAD  16
#define DHEAD  64
#define DINNER 4096
#define MEMLEN 1024
#define KLEN   2048          // QLEN + MEMLEN
#define LN_EPS 1e-5f

// ---------------- scratch (device globals; no allocation allowed) ----------------
__device__ float g_wheads [(size_t)8192 * 3072];        // cat @ qkv_w   [row=j*B+b][3*1024]
__device__ float g_rheadk [(size_t)2048 * 1024];        // r @ r_net_w   [jj][n*64+d]
__device__ float g_attnvec[(size_t)4096 * 1024];        // [i*B+b][n*64+d]
__device__ float g_pre    [(size_t)4096 * 1024];        // pre-layernorm buffer (reused)
__device__ float g_out1   [(size_t)4096 * 1024];        // LN1 output (also FFN residual)
__device__ float g_ffh    [(size_t)4096 * 4096];        // relu(out1@ff_w1+b1)

__device__ __forceinline__ float* gbuf(int id) {
    switch (id) {
        case 0: return g_wheads;
        case 1: return g_rheadk;
        case 2: return g_attnvec;
        case 3: return g_pre;
        case 4: return g_out1;
        case 5: return g_ffh;
    }
    return nullptr;
}

// ---------------- tf32 tensor-core helpers ----------------
__device__ __forceinline__ void mma_tf32(float (&d)[4], const uint32_t (&a)[4],
                                         uint32_t b0, uint32_t b1) {
    asm volatile(
        "mma.sync.aligned.m16n8k8.row.col.f32.tf32.tf32.f32 "
        "{%0,%1,%2,%3}, {%4,%5,%6,%7}, {%8,%9}, {%0,%1,%2,%3};"
        : "+f"(d[0]), "+f"(d[1]), "+f"(d[2]), "+f"(d[3])
        : "r"(a[0]), "r"(a[1]), "r"(a[2]), "r"(a[3]), "r"(b0), "r"(b1));
}

__device__ __forceinline__ void cp16(void* smem, const void* gmem) {
    uint32_t s = (uint32_t)__cvta_generic_to_shared(smem);
    asm volatile("cp.async.cg.shared.global [%0], [%1], 16;" :: "r"(s), "l"(gmem));
}

__device__ __forceinline__ uint32_t tf32r(float f) {   // round-to-nearest tf32
    uint32_t u;
    asm("cvt.rna.tf32.f32 %0, %1;" : "=r"(u) : "f"(f));
    return u;
}

// ---------------- tf32 tensor-core GEMM v2: 3-stage pipeline, 2 CTA/SM --------
// C[Mr,Nc] = A[Mr,Kd] @ B[Kd,Nc]  (+ bias / relu / residual)
// 128x128 block, BK=16, 256 threads (8 warps: 4 M x 2 N), warp tile 32x64.
// 3-stage circular cp.async pipeline, ONE __syncthreads per K-chunk.
// Dynamic smem: As[3][128][20] + Bs[3][16][136]
#define GEMM_STAGES 3
#define GEMM_SMEM_FLOATS (GEMM_STAGES * (128 * 20 + 16 * 136))
#define GEMM_SMEM_BYTES  (GEMM_SMEM_FLOATS * 4)

template<int EPI, int AID, int CID, int RID>
__global__ __launch_bounds__(256, 2)
void gemm_tc(const float* __restrict__ A1p, const float* __restrict__ A2p, int Asplit,
             const float* __restrict__ B, int Nc, int Kd,
             const float* __restrict__ bias, const float* __restrict__ residp)
{
    const float* A1 = (AID >= 0) ? gbuf(AID) : A1p;
    const float* A2 = A2p;
    float*       C  = gbuf(CID);
    const float* RS = (RID >= 0) ? gbuf(RID) : residp;

    extern __shared__ float sm_[];
    float* AsBase = sm_;                                // [S][128][20]
    float* BsBase = sm_ + GEMM_STAGES * 128 * 20;       // [S][16][136]

    const int tid  = threadIdx.x;
    const int lane = tid & 31, warp = tid >> 5;
    const int wm = warp & 3, wn = warp >> 2;
    const int row0 = blockIdx.y * 128, col0 = blockIdx.x * 128;

    const int ar0 = tid >> 2, ac = (tid & 3) * 4;
    const int br0 = tid >> 5, bc = (tid & 31) * 4;

    const int gra0 = row0 + ar0, gra1 = row0 + ar0 + 64;
    const float* arow0 = (gra0 < Asplit) ? A1 + (size_t)gra0 * Kd
                                         : A2 + (size_t)(gra0 - Asplit) * Kd;
    const float* arow1 = (gra1 < Asplit) ? A1 + (size_t)gra1 * Kd
                                         : A2 + (size_t)(gra1 - Asplit) * Kd;

    auto issue = [&](int kt, int stg) {
        const int k0 = kt * 16;
        float* As = AsBase + (size_t)stg * 128 * 20;
        float* Bs = BsBase + (size_t)stg * 16 * 136;
        cp16(&As[(ar0     ) * 20 + ac], arow0 + k0 + ac);
        cp16(&As[(ar0 + 64) * 20 + ac], arow1 + k0 + ac);
        cp16(&Bs[(br0    ) * 136 + bc], B + (size_t)(k0 + br0    ) * Nc + col0 + bc);
        cp16(&Bs[(br0 + 8) * 136 + bc], B + (size_t)(k0 + br0 + 8) * Nc + col0 + bc);
        asm volatile("cp.async.commit_group;");
    };

    float acc[2][8][4];
    #pragma unroll
    for (int mt = 0; mt < 2; mt++)
        #pragma unroll
        for (int nt = 0; nt < 8; nt++)
            #pragma unroll
            for (int e = 0; e < 4; e++) acc[mt][nt][e] = 0.f;

    const int r = lane >> 2, c = lane & 3;
    const int m0 = wm * 32, n0 = wn * 64;

    const int nK = Kd >> 4;
    issue(0, 0);
    if (nK > 1) issue(1, 1);

    int stg = 0;
    for (int kt = 0; kt < nK; kt++) {
        if (kt + 1 < nK) {
            asm volatile("cp.async.wait_group 1;" ::: "memory");
        } else {
            asm volatile("cp.async.wait_group 0;" ::: "memory");
        }
        __syncthreads();   // stage `stg` ready for all; prev compute finished by all

        const uint32_t* Ab = (const uint32_t*)(AsBase + (size_t)stg * 128 * 20);
        const uint32_t* Bb = (const uint32_t*)(BsBase + (size_t)stg * 16 * 136);
        #pragma unroll
        for (int ks = 0; ks < 2; ks++) {
            const int kb = ks * 8;
            uint32_t a[2][4];
            #pragma unroll
            for (int mt = 0; mt < 2; mt++) {
                const int mm = m0 + mt * 16;
                a[mt][0] = Ab[(mm + r    ) * 20 + kb + c];
                a[mt][1] = Ab[(mm + r + 8) * 20 + kb + c];
                a[mt][2] = Ab[(mm + r    ) * 20 + kb + c + 4];
                a[mt][3] = Ab[(mm + r + 8) * 20 + kb + c + 4];
            }
            #pragma unroll
            for (int nt = 0; nt < 8; nt++) {
                const int nn = n0 + nt * 8 + r;
                uint32_t b0 = Bb[(kb + c    ) * 136 + nn];
                uint32_t b1 = Bb[(kb + c + 4) * 136 + nn];
                mma_tf32(acc[0][nt], a[0], b0, b1);
                mma_tf32(acc[1][nt], a[1], b0, b1);
            }
        }

        // refill the stage freed two iterations ago (synced above)
        if (kt + 2 < nK) {
            int ns = stg + 2; if (ns >= GEMM_STAGES) ns -= GEMM_STAGES;
            issue(kt + 2, ns);
        }
        stg = (stg + 1 == GEMM_STAGES) ? 0 : stg + 1;
    }

    #pragma unroll
    for (int mt = 0; mt < 2; mt++) {
        #pragma unroll
        for (int hh = 0; hh < 2; hh++) {
            const int gr = row0 + m0 + mt * 16 + r + hh * 8;
            float* crow = C + (size_t)gr * Nc;
            const float* rrow = (EPI == 2 || EPI == 3) ? RS + (size_t)gr * Nc : nullptr;
            #pragma unroll
            for (int nt = 0; nt < 8; nt++) {
                const int gc = col0 + n0 + nt * 8 + c * 2;
                float v0 = acc[mt][nt][hh * 2 + 0];
                float v1 = acc[mt][nt][hh * 2 + 1];
                if (EPI == 1 || EPI == 2) { v0 += bias[gc]; v1 += bias[gc + 1]; }
                if (EPI == 1) { v0 = fmaxf(v0, 0.f); v1 = fmaxf(v1, 0.f); }
                if (EPI == 2 || EPI == 3) { v0 += rrow[gc]; v1 += rrow[gc + 1]; }
                float2 o = make_float2(v0, v1);
                *(float2*)(crow + gc) = o;
            }
        }
    }
}

// ---------------- fused flash attention (unchanged, proven R8) ----------------
#define AF_SMEM_FLOATS (64*68 + 64 + 64*68 + 128*68 + 2*64*72 + 64*132 + 64*68)
__global__ __launch_bounds__(256)
void attn_flash(const float* __restrict__ rwbias, const float* __restrict__ rrbias)
{
    extern __shared__ float smem[];
    float* Qw    = smem;                    // [64][68]
    float* delta = Qw + 64 * 68;            // [64]
    float* Ks    = delta + 64;              // [64][68]
    float* Rw    = Ks + 64 * 68;            // [128][68]
    float* Vs    = Rw + 128 * 68;           // [2][64][72]
    float* BDst  = Vs + 2 * 64 * 72;        // [64][132]
    float* Pst   = BDst + 64 * 132;         // [64][68]

    const int it = blockIdx.x, bn = blockIdx.y;
    const int n = bn & 15, b = bn >> 4;
    const int i0 = it * 64;
    const int tid = threadIdx.x;
    const int lane = tid & 31, warp = tid >> 5;
    const int r = lane >> 2, c = lane & 3;
    const int m0  = (warp >> 1) * 16;
    const int half = warp & 1;
    const int n0a = half * 32;
    const int n0d = half * 64;
    const int n0v = half * 32;

    const int jtiles = ((i0 + 63 + MEMLEN) >> 6) + 1;

    if (tid < 16) {
        float4 rw = *(const float4*)(rwbias + n * 64 + tid * 4);
        float4 rr = *(const float4*)(rrbias + n * 64 + tid * 4);
        delta[tid * 4 + 0] = rr.x - rw.x;
        delta[tid * 4 + 1] = rr.y - rw.y;
        delta[tid * 4 + 2] = rr.z - rw.z;
        delta[tid * 4 + 3] = rr.w - rw.w;
    }
    #pragma unroll
    for (int l = 0; l < 4; l++) {
        int v = l * 256 + tid;
        int rr = v >> 4, c4 = v & 15;
        float4 q = *(const float4*)(g_wheads
                    + (size_t)((MEMLEN + i0 + rr) * BSZ + b) * 3072 + n * 64 + c4 * 4);
        float4 rw = *(const float4*)(rwbias + n * 64 + c4 * 4);
        Qw[rr * 68 + c4 * 4 + 0] = q.x + rw.x;
        Qw[rr * 68 + c4 * 4 + 1] = q.y + rw.y;
        Qw[rr * 68 + c4 * 4 + 2] = q.z + rw.z;
        Qw[rr * 68 + c4 * 4 + 3] = q.w + rw.w;
    }

    auto issue = [&](int jt, int vbuf) {
        const int j0c  = jt * 64;
        const int r_lo = (QLEN - 1) + j0c - i0 - 63;
        #pragma unroll
        for (int l = 0; l < 4; l++) {
            int v = l * 256 + tid;
            int rr = v >> 4, c4 = v & 15;
            cp16(&Ks[rr * 68 + c4 * 4],
                 g_wheads + (size_t)((j0c + rr) * BSZ + b) * 3072 + 1024 + n * 64 + c4 * 4);
        }
        #pragma unroll
        for (int l = 0; l < 8; l++) {
            int v = l * 256 + tid;
            int rr = v >> 4, c4 = v & 15;
            int grow = r_lo + rr; if (grow > KLEN - 1) grow = KLEN - 1;
            cp16(&Rw[rr * 68 + c4 * 4],
                 g_rheadk + (size_t)grow * 1024 + n * 64 + c4 * 4);
        }
        #pragma unroll
        for (int l = 0; l < 4; l++) {
            int v = l * 256 + tid;
            int rr = v >> 4, c4 = v & 15;
            cp16(&Vs[(size_t)vbuf * 64 * 72 + rr * 72 + c4 * 4],
                 g_wheads + (size_t)((j0c + rr) * BSZ + b) * 3072 + 2048 + n * 64 + c4 * 4);
        }
        asm volatile("cp.async.commit_group;");
    };

    float accO[4][4];
    #pragma unroll
    for (int nt = 0; nt < 4; nt++)
        #pragma unroll
        for (int e = 0; e < 4; e++) accO[nt][e] = 0.f;
    float M0 = -1e30f, M1 = -1e30f, l0 = 0.f, l1 = 0.f;

    issue(0, 0);

    for (int jt = 0; jt < jtiles; jt++) {
        const int j0c = jt * 64;
        const int vbuf = jt & 1;
        asm volatile("cp.async.wait_group 0;" ::: "memory");
        __syncthreads();

        float accA[4][4], accB[8][4];
        #pragma unroll
        for (int nt = 0; nt < 4; nt++)
            #pragma unroll
            for (int e = 0; e < 4; e++) accA[nt][e] = 0.f;
        #pragma unroll
        for (int nt = 0; nt < 8; nt++)
            #pragma unroll
            for (int e = 0; e < 4; e++) accB[nt][e] = 0.f;

        #pragma unroll
        for (int ks = 0; ks < 8; ks++) {
            const int kb = ks * 8;
            float a0 = Qw[(m0 + r    ) * 68 + kb + c];
            float a1 = Qw[(m0 + r + 8) * 68 + kb + c];
            float a2 = Qw[(m0 + r    ) * 68 + kb + c + 4];
            float a3 = Qw[(m0 + r + 8) * 68 + kb + c + 4];
            float d0 = delta[kb + c], d1 = delta[kb + c + 4];
            uint32_t aw[4] = { tf32r(a0), tf32r(a1), tf32r(a2), tf32r(a3) };
            uint32_t ar[4] = { tf32r(a0 + d0), tf32r(a1 + d0),
                               tf32r(a2 + d1), tf32r(a3 + d1) };
            #pragma unroll
            for (int nt = 0; nt < 4; nt++) {
                int nn = n0a + nt * 8 + r;
                uint32_t b0 = tf32r(Ks[nn * 68 + kb + c]);
                uint32_t b1 = tf32r(Ks[nn * 68 + kb + c + 4]);
                mma_tf32(accA[nt], aw, b0, b1);
            }
            #pragma unroll
            for (int nt = 0; nt < 8; nt++) {
                int nn = n0d + nt * 8 + r;
                uint32_t b0 = tf32r(Rw[nn * 68 + kb + c]);
                uint32_t b1 = tf32r(Rw[nn * 68 + kb + c + 4]);
                mma_tf32(accB[nt], ar, b0, b1);
            }
        }

        __syncthreads();
        if (jt + 1 < jtiles) issue(jt + 1, vbuf ^ 1);

        #pragma unroll
        for (int nt = 0; nt < 8; nt++) {
            int col = n0d + nt * 8 + 2 * c;
            BDst[(m0 + r    ) * 132 + col    ] = accB[nt][0];
            BDst[(m0 + r    ) * 132 + col + 1] = accB[nt][1];
            BDst[(m0 + r + 8) * 132 + col    ] = accB[nt][2];
            BDst[(m0 + r + 8) * 132 + col + 1] = accB[nt][3];
        }
        __syncthreads();

        #pragma unroll
        for (int nt = 0; nt < 4; nt++) {
            #pragma unroll
            for (int e = 0; e < 4; e++) {
                int ii  = m0 + r + ((e & 2) ? 8 : 0);
                int jjl = n0a + nt * 8 + 2 * c + (e & 1);
                float s = (accA[nt][e] + BDst[ii * 132 + (jjl - ii + 63)]) * 0.125f;
                if (j0c + jjl > i0 + ii + MEMLEN) s = -1e30f;
                Pst[ii * 68 + jjl] = s;
            }
        }
        __syncthreads();

        float cm0 = -1e30f, cm1 = -1e30f;
        #pragma unroll
        for (int ks = 0; ks < 8; ks++) {
            const int kb = ks * 8;
            cm0 = fmaxf(cm0, fmaxf(Pst[(m0 + r    ) * 68 + kb + c],
                                   Pst[(m0 + r    ) * 68 + kb + c + 4]));
            cm1 = fmaxf(cm1, fmaxf(Pst[(m0 + r + 8) * 68 + kb + c],
                                   Pst[(m0 + r + 8) * 68 + kb + c + 4]));
        }
        cm0 = fmaxf(cm0, __shfl_xor_sync(0xffffffffu, cm0, 1));
        cm0 = fmaxf(cm0, __shfl_xor_sync(0xffffffffu, cm0, 2));
        cm1 = fmaxf(cm1, __shfl_xor_sync(0xffffffffu, cm1, 1));
        cm1 = fmaxf(cm1, __shfl_xor_sync(0xffffffffu, cm1, 2));
        const float M0n = fmaxf(M0, cm0), M1n = fmaxf(M1, cm1);
        const float f0 = __expf(M0 - M0n), f1 = __expf(M1 - M1n);
        M0 = M0n; M1 = M1n;
        l0 *= f0; l1 *= f1;
        #pragma unroll
        for (int nt = 0; nt < 4; nt++) {
            accO[nt][0] *= f0; accO[nt][1] *= f0;
            accO[nt][2] *= f1; accO[nt][3] *= f1;
        }

        const float* Vb = Vs + (size_t)vbuf * 64 * 72;
        #pragma unroll
        for (int ks = 0; ks < 8; ks++) {
            const int kb = ks * 8;
            float p0 = __expf(Pst[(m0 + r    ) * 68 + kb + c    ] - M0);
            float p1 = __expf(Pst[(m0 + r + 8) * 68 + kb + c    ] - M1);
            float p2 = __expf(Pst[(m0 + r    ) * 68 + kb + c + 4] - M0);
            float p3 = __expf(Pst[(m0 + r + 8) * 68 + kb + c + 4] - M1);
            l0 += p0 + p2;
            l1 += p1 + p3;
            uint32_t a[4] = { tf32r(p0), tf32r(p1), tf32r(p2), tf32r(p3) };
            #pragma unroll
            for (int nt = 0; nt < 4; nt++) {
                int nn = n0v + nt * 8 + r;
                uint32_t b0 = tf32r(Vb[(kb + c    ) * 72 + nn]);
                uint32_t b1 = tf32r(Vb[(kb + c + 4) * 72 + nn]);
                mma_tf32(accO[nt], a, b0, b1);
            }
        }
        __syncthreads();
    }

    l0 += __shfl_xor_sync(0xffffffffu, l0, 1);
    l0 += __shfl_xor_sync(0xffffffffu, l0, 2);
    l1 += __shfl_xor_sync(0xffffffffu, l1, 1);
    l1 += __shfl_xor_sync(0xffffffffu, l1, 2);
    const float inv0 = 1.f / l0, inv1 = 1.f / l1;
    #pragma unroll
    for (int nt = 0; nt < 4; nt++) {
        const int dd = n0v + nt * 8 + 2 * c;
        const int row0 = i0 + m0 + r, row1 = row0 + 8;
        *(float2*)(g_attnvec + (size_t)(row0 * BSZ + b) * 1024 + n * 64 + dd)
            = make_float2(accO[nt][0] * inv0, accO[nt][1] * inv0);
        *(float2*)(g_attnvec + (size_t)(row1 * BSZ + b) * 1024 + n * 64 + dd)
            = make_float2(accO[nt][2] * inv1, accO[nt][3] * inv1);
    }
}

// ---------------- layernorm over D=1024 ----------------
__global__ __launch_bounds__(256)
void ln_k(float* __restrict__ yext, const float* __restrict__ gam, const float* __restrict__ bet)
{
    const float* row = g_pre + (size_t)blockIdx.x * DMODEL;
    float* orow = (yext ? yext : g_out1) + (size_t)blockIdx.x * DMODEL;
    const int tid = threadIdx.x;
    float v[4];
    float s = 0.f, sq = 0.f;
    #pragma unroll
    for (int e = 0; e < 4; e++) {
        v[e] = row[e * 256 + tid];
        s  += v[e];
        sq += v[e] * v[e];
    }
    #pragma unroll
    for (int off = 16; off; off >>= 1) {
        s  += __shfl_xor_sync(0xffffffffu, s,  off);
        sq += __shfl_xor_sync(0xffffffffu, sq, off);
    }
    __shared__ float sm[8], sm2[8];
    if ((tid & 31) == 0) { sm[tid >> 5] = s; sm2[tid >> 5] = sq; }
    __syncthreads();
    float S = 0.f, SQ = 0.f;
    #pragma unroll
    for (int w = 0; w < 8; w++) { S += sm[w]; SQ += sm2[w]; }
    const float mu  = S * (1.f / DMODEL);
    const float var = SQ * (1.f / DMODEL) - mu * mu;
    const float inv = rsqrtf(var + LN_EPS);
    #pragma unroll
    for (int e = 0; e < 4; e++) {
        int c = e * 256 + tid;
        orow[c] = (v[e] - mu) * inv * gam[c] + bet[c];
    }
}

// ---------------- launch ----------------
extern "C" void kernel_launch(void* const* d_in, const int* in_sizes, int n_in,
                              void* d_out, int out_size)
{
    const float* w        = (const float*)d_in[0];
    const float* r        = (const float*)d_in[1];
    const float* mems     = (const float*)d_in[2];
    const float* qkv_w    = (const float*)d_in[3];
    const float* r_net_w  = (const float*)d_in[4];
    const float* o_w      = (const float*)d_in[5];
    const float* r_w_bias = (const float*)d_in[6];
    const float* r_r_bias = (const float*)d_in[7];
    const float* ln1_g    = (const float*)d_in[8];
    const float* ln1_b    = (const float*)d_in[9];
    const float* ff_w1    = (const float*)d_in[10];
    const float* ff_b1    = (const float*)d_in[11];
    const float* ff_w2    = (const float*)d_in[12];
    const float* ff_b2    = (const float*)d_in[13];
    const float* ln2_g    = (const float*)d_in[14];
    const float* ln2_b    = (const float*)d_in[15];
    float* out = (float*)d_out;

    const dim3 t256(256);
    const int NOSPLIT = 1 << 30;

    static bool attr_done = false;
    if (!attr_done) {
        cudaFuncSetAttribute(attn_flash, cudaFuncAttributeMaxDynamicSharedMemorySize,
                             AF_SMEM_FLOATS * 4);
        cudaFuncSetAttribute(gemm_tc<0, -1, 0, -1>,
                             cudaFuncAttributeMaxDynamicSharedMemorySize, GEMM_SMEM_BYTES);
        cudaFuncSetAttribute(gemm_tc<0, -1, 1, -1>,
                             cudaFuncAttributeMaxDynamicSharedMemorySize, GEMM_SMEM_BYTES);
        cudaFuncSetAttribute(gemm_tc<3, 2, 3, -1>,
                             cudaFuncAttributeMaxDynamicSharedMemorySize, GEMM_SMEM_BYTES);
        cudaFuncSetAttribute(gemm_tc<1, 4, 5, -1>,
                             cudaFuncAttributeMaxDynamicSharedMemorySize, GEMM_SMEM_BYTES);
        cudaFuncSetAttribute(gemm_tc<2, 5, 3, 4>,
                             cudaFuncAttributeMaxDynamicSharedMemorySize, GEMM_SMEM_BYTES);
        attr_done = true;
    }

    // 1) w_heads = [mems; w] @ qkv_w
    gemm_tc<0, -1, 0, -1><<<dim3(24, 64), t256, GEMM_SMEM_BYTES>>>(
        mems, w, MEMLEN * BSZ, qkv_w, 3072, 1024, nullptr, nullptr);
    // 2) r_head_k = r @ r_net_w
    gemm_tc<0, -1, 1, -1><<<dim3(8, 16), t256, GEMM_SMEM_BYTES>>>(
        r, nullptr, NOSPLIT, r_net_w, 1024, 1024, nullptr, nullptr);
    // 3) fused: scores + online softmax + P@V  -> g_attnvec
    attn_flash<<<dim3(16, 64), t256, AF_SMEM_FLOATS * 4>>>(r_w_bias, r_r_bias);
    // 4) pre1 = w + attn_vec @ o_w
    gemm_tc<3, 2, 3, -1><<<dim3(8, 32), t256, GEMM_SMEM_BYTES>>>(
        nullptr, nullptr, NOSPLIT, o_w, 1024, 1024, nullptr, w);
    // 5) out1 = LN1(pre1)
    ln_k<<<4096, t256>>>(nullptr, ln1_g, ln1_b);
    // 6) h = relu(out1 @ ff_w1 + b1)
    gemm_tc<1, 4, 5, -1><<<dim3(32, 32), t256, GEMM_SMEM_BYTES>>>(
        nullptr, nullptr, NOSPLIT, ff_w1, 4096, 1024, ff_b1, nullptr);
    // 7) pre2 = out1 + h @ ff_w2 + b2
    gemm_tc<2, 5, 3, 4><<<dim3(8, 32), t256, GEMM_SMEM_BYTES>>>(
        nullptr, nullptr, NOSPLIT, ff_w2, 1024, 4096, ff_b2, nullptr);
    // 8) out = LN2(pre2)
    ln_k<<<4096, t256>>>(out, ln2_g, ln2_b);
}